// round 14
// baseline (speedup 1.0000x reference)
#include <cuda_runtime.h>
#include <cuda_fp16.h>
#include <math.h>
#include <stdint.h>

#define BATCH 4
#define SEQ   4096
#define DMODEL 1024
#define DFF   4096
#define MTOK  (BATCH*SEQ)

// ---- dual-B kernel: 512 threads, BKK=64, 4 stages ----
#define BM 128
#define BN 128
#define DKK 64
#define HSTR_D 72                                    // 64 + 8 pad halfs
#define DSTAGES 4
#define DSTAGE_HALFS ((BM + 2*BN) * HSTR_D)          // 27648 halfs = 55296 B
#define DSMEM (DSTAGES * DSTAGE_HALFS * 2)           // 221184

// ---- single-B (W2): 256 threads, BKK=64, 3 stages, 2 CTAs/SM ----
#define SKK 64
#define HSTR_S 72
#define SSTAGES 3
#define SSTAGE_HALFS ((BM + BN) * HSTR_S)            // 18432 halfs = 36864 B
#define SSMEM (SSTAGES * SSTAGE_HALFS * 2)           // 110592

#define M_GATES 0
#define M_FF    1

// fused residual+norm kernel: fp16 slab, 256 threads, 2 CTAs/SM
#define FR_HSTR 1026
#define FRSMEM (32 * FR_HSTR * 2)                    // 65664

// ------------------------- scratch -----------------------------------------
__device__ __half g_hin[MTOK*DMODEL];
__device__ __half g_fin[MTOK*DMODEL];
__device__ __half g_at [BATCH*DMODEL*SEQ];           // gates, fp16 [b,d,t]
__device__ __half g_bt [BATCH*DMODEL*SEQ];           // (1-g)*c -> h, fp16 [b,d,t]
__device__ __half g_u  [(size_t)MTOK*DFF];
__device__ __half g_WgT[DMODEL*DMODEL];
__device__ __half g_WcT[DMODEL*DMODEL];
__device__ __half g_W1T[(size_t)DFF*DMODEL];
__device__ __half g_W3T[(size_t)DFF*DMODEL];
__device__ __half g_W2T[(size_t)DMODEL*DFF];

// ------------------------- helpers -----------------------------------------
__device__ __forceinline__ uint32_t smem_u32(const void* p) {
    uint32_t a;
    asm("{ .reg .u64 t; cvta.to.shared.u64 t, %1; cvt.u32.u64 %0, t; }"
        : "=r"(a) : "l"(p));
    return a;
}
#define CPA16(dst, src) \
    asm volatile("cp.async.cg.shared.global [%0], [%1], 16;" :: "r"(dst), "l"(src))
#define CPA_COMMIT() asm volatile("cp.async.commit_group;" ::: "memory")
#define CPA_WAITG(n) asm volatile("cp.async.wait_group %0;" :: "n"(n) : "memory")

__device__ __forceinline__ void hmma(float c[4], const uint32_t a[4], const uint32_t b[2]) {
    asm volatile(
        "mma.sync.aligned.m16n8k16.row.col.f32.f16.f16.f32 "
        "{%0,%1,%2,%3},{%4,%5,%6,%7},{%8,%9},{%0,%1,%2,%3};"
        : "+f"(c[0]), "+f"(c[1]), "+f"(c[2]), "+f"(c[3])
        : "r"(a[0]), "r"(a[1]), "r"(a[2]), "r"(a[3]), "r"(b[0]), "r"(b[1]));
}
__device__ __forceinline__ void ldsm4(uint32_t& r0, uint32_t& r1, uint32_t& r2,
                                      uint32_t& r3, uint32_t addr) {
    asm volatile("ldmatrix.sync.aligned.m8n8.x4.shared.b16 {%0,%1,%2,%3}, [%4];"
                 : "=r"(r0), "=r"(r1), "=r"(r2), "=r"(r3) : "r"(addr));
}
__device__ __forceinline__ int a_lm_off(int lane, int stride) {
    return (lane & 15) * stride + 8 * (lane >> 4);
}
__device__ __forceinline__ int b_lm_off(int lane, int stride) {
    return ((lane & 7) + 8 * (lane >> 4)) * stride + 8 * ((lane >> 3) & 1);
}

// ------------------------- dual-B fp16 GEMM (512 thr, 4 stages) ------------
// Next-stage loads issued BEFORE compute (overlap LSU burst with HMMA).
template<int MODE>
__global__ __launch_bounds__(512, 1) void gemm_dual(
    const __half* __restrict__ A, const __half* __restrict__ B1T,
    const __half* __restrict__ B2T,
    __half* __restrict__ O1, __half* __restrict__ O2, __half* __restrict__ OU,
    const float* __restrict__ bias1, const float* __restrict__ bias2,
    int K)
{
    extern __shared__ __half smh[];
    const uint32_t sbase = smem_u32(smh);
    const int tid = threadIdx.x, lane = tid & 31, wid = tid >> 5;
    const int wm = wid & 3, wn = wid >> 2;     // 4x4 warps, 32x32 tile each
    const int m0 = blockIdx.y * BM, n0 = blockIdx.x * BN;
    const int NK = K / DKK;

    const int aoff = a_lm_off(lane, HSTR_D);
    const int boff = b_lm_off(lane, HSTR_D);

    float acc1[2][4][4] = {};
    float acc2[2][4][4] = {};

    #define DLOAD(stage, ktile)                                                   \
    {                                                                             \
        uint32_t base = sbase + (stage) * DSTAGE_HALFS * 2;                       \
        long koff = (long)(ktile) * DKK;                                          \
        _Pragma("unroll")                                                         \
        for (int i = 0; i < 6; i++) {                                             \
            int id = tid + i * 512;                                               \
            int row = id >> 3, ch = (id & 7) * 8;                                 \
            const __half* src;                                                    \
            if (row < 128)      src = A   + (long)(m0 + row)       * K + koff + ch; \
            else if (row < 256) src = B1T + (long)(n0 + row - 128) * K + koff + ch; \
            else                src = B2T + (long)(n0 + row - 256) * K + koff + ch; \
            CPA16(base + (row * HSTR_D + ch) * 2, src);                           \
        }                                                                         \
        CPA_COMMIT();                                                             \
    }

    #pragma unroll
    for (int ps = 0; ps < DSTAGES - 1; ps++) DLOAD(ps, ps);

    for (int kt = 0; kt < NK; kt++) {
        CPA_WAITG(DSTAGES - 2);
        __syncthreads();
        // issue next-stage loads FIRST, then compute over the ready stage
        int nxt = kt + DSTAGES - 1;
        if (nxt < NK) DLOAD(nxt % DSTAGES, nxt)
        else CPA_COMMIT();

        uint32_t stg = sbase + (kt % DSTAGES) * DSTAGE_HALFS * 2;
        uint32_t As  = stg;
        uint32_t B1s = stg + BM * HSTR_D * 2;
        uint32_t B2s = stg + (BM + BN) * HSTR_D * 2;
        #pragma unroll
        for (int ks = 0; ks < 4; ks++) {
            const int k0 = ks * 16;
            uint32_t af[2][4], bf1[4][2], bf2[4][2];
            #pragma unroll
            for (int i = 0; i < 2; i++) {
                uint32_t ad = As + ((wm*32 + i*16) * HSTR_D + k0 + aoff) * 2;
                ldsm4(af[i][0], af[i][1], af[i][2], af[i][3], ad);
            }
            #pragma unroll
            for (int jp = 0; jp < 2; jp++) {
                uint32_t bd1 = B1s + ((wn*32 + jp*16) * HSTR_D + k0 + boff) * 2;
                uint32_t bd2 = B2s + ((wn*32 + jp*16) * HSTR_D + k0 + boff) * 2;
                ldsm4(bf1[jp*2][0], bf1[jp*2][1], bf1[jp*2+1][0], bf1[jp*2+1][1], bd1);
                ldsm4(bf2[jp*2][0], bf2[jp*2][1], bf2[jp*2+1][0], bf2[jp*2+1][1], bd2);
            }
            #pragma unroll
            for (int i = 0; i < 2; i++)
                #pragma unroll
                for (int j = 0; j < 4; j++) {
                    hmma(acc1[i][j], af[i], bf1[j]);
                    hmma(acc2[i][j], af[i], bf2[j]);
                }
        }
    }
    __syncthreads();   // smem reused for epilogue patches

    if (MODE == M_FF) {
        __half2* patch = (__half2*)smh + wid * (32 * 36);
        #pragma unroll
        for (int i = 0; i < 2; i++) {
            #pragma unroll
            for (int j = 0; j < 4; j++) {
                int r0 = i*16 + (lane>>2);
                int ch = j*4 + (lane&3);
                float a0 = acc1[i][j][0], a1 = acc1[i][j][1];
                float a2 = acc1[i][j][2], a3 = acc1[i][j][3];
                float v0 = a0 / (1.f + __expf(-a0)) * acc2[i][j][0];
                float v1 = a1 / (1.f + __expf(-a1)) * acc2[i][j][1];
                float v2 = a2 / (1.f + __expf(-a2)) * acc2[i][j][2];
                float v3 = a3 / (1.f + __expf(-a3)) * acc2[i][j][3];
                patch[r0*36 + ch]     = __floats2half2_rn(v0, v1);
                patch[(r0+8)*36 + ch] = __floats2half2_rn(v2, v3);
            }
        }
        __syncwarp();
        int tok0 = m0 + wm * 32;
        int cb = n0 + wn * 32;
        #pragma unroll
        for (int r2 = 0; r2 < 32; r2 += 2) {
            int rr = r2 + (lane >> 4);
            int cc = lane & 15;
            *(__half2*)(OU + (long)(tok0 + rr) * DFF + cb + cc*2) = patch[rr*36 + cc];
        }
    } else {
        float* patchG = (float*)smh + wid * 2 * (32 * 33);
        float* patchH = patchG + 32 * 33;
        #pragma unroll
        for (int i = 0; i < 2; i++) {
            #pragma unroll
            for (int j = 0; j < 4; j++) {
                int r0 = i*16 + (lane>>2);            // t-local 0..31
                int c0 = j*8 + 2*(lane&3);            // n-local 0..31
                int n  = n0 + wn*32 + c0;
                float b1a = bias1[n], b1b = bias1[n+1];
                float b2a = bias2[n], b2b = bias2[n+1];
                float g0 = 1.f / (1.f + __expf(-(acc1[i][j][0] + b1a)));
                float g1 = 1.f / (1.f + __expf(-(acc1[i][j][1] + b1b)));
                float g2 = 1.f / (1.f + __expf(-(acc1[i][j][2] + b1a)));
                float g3 = 1.f / (1.f + __expf(-(acc1[i][j][3] + b1b)));
                float h0 = (1.f - g0) * tanhf(acc2[i][j][0] + b2a);
                float h1 = (1.f - g1) * tanhf(acc2[i][j][1] + b2b);
                float h2 = (1.f - g2) * tanhf(acc2[i][j][2] + b2a);
                float h3 = (1.f - g3) * tanhf(acc2[i][j][3] + b2b);
                patchG[c0*33 + r0]       = g0;
                patchG[(c0+1)*33 + r0]   = g1;
                patchG[c0*33 + r0+8]     = g2;
                patchG[(c0+1)*33 + r0+8] = g3;
                patchH[c0*33 + r0]       = h0;
                patchH[(c0+1)*33 + r0]   = h1;
                patchH[c0*33 + r0+8]     = h2;
                patchH[(c0+1)*33 + r0+8] = h3;
            }
        }
        __syncwarp();
        int tokb = m0 + wm * 32;
        int b = tokb >> 12, tb = tokb & 4095;
        #pragma unroll 4
        for (int r = 0; r < 32; r++) {
            int n = n0 + wn*32 + r;
            long off = ((long)(b * DMODEL + n)) * SEQ + tb + lane;
            O1[off] = __float2half_rn(patchG[r*33 + lane]);
            O2[off] = __float2half_rn(patchH[r*33 + lane]);
        }
    }
    #undef DLOAD
}

// --------- single-B fp16 GEMM: O += A@BT^T (BKK=64, 3 stages, 2/SM) --------
__global__ __launch_bounds__(256, 2) void gemm_res(
    const __half* __restrict__ A, const __half* __restrict__ BT,
    float* __restrict__ O, int K, int ldo)
{
    extern __shared__ __half smh[];
    const uint32_t sbase = smem_u32(smh);
    const int tid = threadIdx.x, lane = tid & 31, wid = tid >> 5;
    const int wm = wid & 1, wn = wid >> 1;
    const int m0 = blockIdx.y * BM, n0 = blockIdx.x * BN;
    const int NK = K / SKK;

    const int aoff = a_lm_off(lane, HSTR_S);
    const int boff = b_lm_off(lane, HSTR_S);

    float acc[4][4][4] = {};

    #define SLOAD(stage, ktile)                                                   \
    {                                                                             \
        uint32_t base = sbase + (stage) * SSTAGE_HALFS * 2;                       \
        long koff = (long)(ktile) * SKK;                                          \
        _Pragma("unroll")                                                         \
        for (int i = 0; i < 8; i++) {                                             \
            int id = tid + i * 256;                                               \
            int row = id >> 3, ch = (id & 7) * 8;                                 \
            const __half* src;                                                    \
            if (row < 128) src = A  + (long)(m0 + row)       * K + koff + ch;     \
            else           src = BT + (long)(n0 + row - 128) * K + koff + ch;     \
            CPA16(base + (row * HSTR_S + ch) * 2, src);                           \
        }                                                                         \
        CPA_COMMIT();                                                             \
    }

    #pragma unroll
    for (int ps = 0; ps < SSTAGES - 1; ps++) SLOAD(ps, ps);

    for (int kt = 0; kt < NK; kt++) {
        CPA_WAITG(SSTAGES - 2);
        __syncthreads();
        int nxt = kt + SSTAGES - 1;
        if (nxt < NK) SLOAD(nxt % SSTAGES, nxt)
        else CPA_COMMIT();

        uint32_t stg = sbase + (kt % SSTAGES) * SSTAGE_HALFS * 2;
        uint32_t As = stg;
        uint32_t Bs = stg + BM * HSTR_S * 2;
        #pragma unroll
        for (int ks = 0; ks < 4; ks++) {
            const int k0 = ks * 16;
            uint32_t af[4][4], bf[4][2];
            #pragma unroll
            for (int i = 0; i < 4; i++) {
                uint32_t ad = As + ((wm*64 + i*16) * HSTR_S + k0 + aoff) * 2;
                ldsm4(af[i][0], af[i][1], af[i][2], af[i][3], ad);
            }
            #pragma unroll
            for (int jp = 0; jp < 2; jp++) {
                uint32_t bd = Bs + ((wn*32 + jp*16) * HSTR_S + k0 + boff) * 2;
                ldsm4(bf[jp*2][0], bf[jp*2][1], bf[jp*2+1][0], bf[jp*2+1][1], bd);
            }
            #pragma unroll
            for (int i = 0; i < 4; i++)
                #pragma unroll
                for (int j = 0; j < 4; j++)
                    hmma(acc[i][j], af[i], bf[j]);
        }
    }

    #pragma unroll
    for (int i = 0; i < 4; i++) {
        #pragma unroll
        for (int j = 0; j < 4; j++) {
            int r0 = m0 + wm*64 + i*16 + (lane>>2);
            int c0 = n0 + wn*32 + j*8 + 2*(lane&3);
            long o0 = (long)r0 * ldo + c0;
            long o1 = o0 + (long)8 * ldo;
            float2 p0 = *(const float2*)(O + o0);
            float2 p1 = *(const float2*)(O + o1);
            *(float2*)(O + o0) = make_float2(acc[i][j][0] + p0.x, acc[i][j][1] + p0.y);
            *(float2*)(O + o1) = make_float2(acc[i][j][2] + p1.x, acc[i][j][3] + p1.y);
        }
    }
    #undef SLOAD
}

// ------ prep: rmsnorm (blocks < MTOK) + all weight transposes (rest) -------
__global__ __launch_bounds__(256) void prep_kernel(
    const float* __restrict__ x, const float* __restrict__ w, __half* __restrict__ y,
    const float* __restrict__ Wg, const float* __restrict__ Wc,
    const float* __restrict__ W1, const float* __restrict__ W3,
    const float* __restrict__ W2,
    __half* __restrict__ WgT, __half* __restrict__ WcT,
    __half* __restrict__ W1T, __half* __restrict__ W3T,
    __half* __restrict__ W2T)
{
    __shared__ float sred[8];
    __shared__ float tile[32][33];
    int bid = blockIdx.x, tid = threadIdx.x;

    if (bid >= MTOK) {
        int s = bid - MTOK;                    // 0..14335
        const float* W; __half* WT; int Kw, Nw, tt;
        if (s < 1024)       { W = Wg; WT = WgT; Kw = DMODEL; Nw = DMODEL; tt = s; }
        else if (s < 2048)  { W = Wc; WT = WcT; Kw = DMODEL; Nw = DMODEL; tt = s - 1024; }
        else if (s < 6144)  { W = W1; WT = W1T; Kw = DMODEL; Nw = DFF;    tt = s - 2048; }
        else if (s < 10240) { W = W3; WT = W3T; Kw = DMODEL; Nw = DFF;    tt = s - 6144; }
        else                { W = W2; WT = W2T; Kw = DFF;    Nw = DMODEL; tt = s - 10240; }
        int ntx = Nw >> 5;
        int n0 = (tt % ntx) * 32, k0 = (tt / ntx) * 32;
        int tx = tid & 31, ty = tid >> 5;
        #pragma unroll
        for (int i = 0; i < 4; i++)
            tile[ty + 8*i][tx] = W[(long)(k0 + ty + 8*i) * Nw + n0 + tx];
        __syncthreads();
        #pragma unroll
        for (int i = 0; i < 4; i++)
            WT[(long)(n0 + ty + 8*i) * Kw + k0 + tx] =
                __float2half_rn(tile[tx][ty + 8*i]);
        return;
    }

    float4 v = ((const float4*)(x + (long)bid * DMODEL))[tid];
    float ss = v.x*v.x + v.y*v.y + v.z*v.z + v.w*v.w;
    #pragma unroll
    for (int o = 16; o; o >>= 1) ss += __shfl_xor_sync(0xffffffffu, ss, o);
    if ((tid & 31) == 0) sred[tid >> 5] = ss;
    __syncthreads();
    if (tid < 8) {
        float t = sred[tid];
        #pragma unroll
        for (int o = 4; o; o >>= 1) t += __shfl_xor_sync(0xffu, t, o);
        if (tid == 0) sred[0] = t;
    }
    __syncthreads();
    float scale = rsqrtf(sred[0] * (1.0f / DMODEL) + 1e-6f);
    float4 wv = ((const float4*)w)[tid];
    __half2 h01 = __floats2half2_rn(v.x*scale*wv.x, v.y*scale*wv.y);
    __half2 h23 = __floats2half2_rn(v.z*scale*wv.z, v.w*scale*wv.w);
    __half2* yp = (__half2*)(y + (long)bid * DMODEL) + tid * 2;
    yp[0] = h01; yp[1] = h23;
}

// ---------- fused: x2 = x + h^T; out=x2 (f32); fin = rmsnorm(x2)*w (fp16) ---
__global__ __launch_bounds__(256) void fuse_res_norm(
    const float* __restrict__ x, const __half* __restrict__ ht,
    const float* __restrict__ w,
    float* __restrict__ out, __half* __restrict__ fin)
{
    extern __shared__ __half hslab[];          // [32][FR_HSTR]
    const int t0 = blockIdx.x * 32, b = blockIdx.y;
    const int tid = threadIdx.x, lane = tid & 31, wid = tid >> 5;

    for (int g = 0; g < 4; g++) {
        for (int dc = 0; dc < 32; dc++) {
            int d = g * 256 + dc * 8 + wid;
            const __half* src = ht + ((long)(b * DMODEL + d)) * SEQ + t0;
            hslab[lane * FR_HSTR + d] = src[lane];
        }
    }
    __syncthreads();

    #pragma unroll
    for (int k = 0; k < 4; k++) {
        int tt = wid * 4 + k;
        int tok = b * SEQ + t0 + tt;
        const __half* row = hslab + tt * FR_HSTR;
        const float* xr = x + (long)tok * DMODEL;
        float ss = 0.f;
        float vals[32];
        #pragma unroll
        for (int q = 0; q < 32; q++) {
            float v = xr[q * 32 + lane] + __half2float(row[q * 32 + lane]);
            vals[q] = v;
            ss += v * v;
        }
        #pragma unroll
        for (int o = 16; o; o >>= 1) ss += __shfl_xor_sync(0xffffffffu, ss, o);
        float scale = rsqrtf(ss * (1.0f / DMODEL) + 1e-6f);
        float* orow = out + (long)tok * DMODEL;
        __half* frow = fin + (long)tok * DMODEL;
        #pragma unroll
        for (int q = 0; q < 32; q++) {
            int d = q * 32 + lane;
            orow[d] = vals[q];
            frow[d] = __float2half_rn(vals[q] * scale * w[d]);
        }
    }
}

// ------------------- scan over t (per (b,d) row, uint4 fp16 I/O) -----------
__global__ __launch_bounds__(256) void scan_kernel(
    const __half* __restrict__ at, __half* __restrict__ bt)
{
    long base = (long)blockIdx.x * SEQ;
    int tid = threadIdx.x;
    float la[16], lb[16];
    const uint4* ap = (const uint4*)(at + base) + tid * 2;
    uint4*       bp = (uint4*)(bt + base) + tid * 2;
    uint4 va[2] = { ap[0], ap[1] };
    uint4 vb[2] = { bp[0], bp[1] };
    #pragma unroll
    for (int q = 0; q < 8; q++) {
        float2 fa = __half22float2(((const __half2*)va)[q]);
        float2 fb = __half22float2(((const __half2*)vb)[q]);
        la[2*q] = fa.x; la[2*q+1] = fa.y;
        lb[2*q] = fb.x; lb[2*q+1] = fb.y;
    }
    float A = 1.f, Bc = 0.f;
    #pragma unroll
    for (int j = 0; j < 16; j++) { Bc = la[j] * Bc + lb[j]; A *= la[j]; }
    __shared__ float sA[256], sB[256];
    sA[tid] = A; sB[tid] = Bc;
    __syncthreads();
    #pragma unroll
    for (int off = 1; off < 256; off <<= 1) {
        float pA = 1.f, pB = 0.f;
        if (tid >= off) { pA = sA[tid - off]; pB = sB[tid - off]; }
        float cA = sA[tid], cB = sB[tid];
        __syncthreads();
        sA[tid] = pA * cA;
        sB[tid] = cA * pB + cB;
        __syncthreads();
    }
    float carry = (tid > 0) ? sB[tid - 1] : 0.f;
    #pragma unroll
    for (int j = 0; j < 16; j++) { carry = la[j] * carry + lb[j]; lb[j] = carry; }
    #pragma unroll
    for (int q = 0; q < 8; q++)
        ((__half2*)vb)[q] = __floats2half2_rn(lb[2*q], lb[2*q+1]);
    bp[0] = vb[0]; bp[1] = vb[1];
}

// ----------------------------------------------------------------------------
extern "C" void kernel_launch(void* const* d_in, const int* in_sizes, int n_in,
                              void* d_out, int out_size)
{
    const float* x   = (const float*)d_in[0];
    const float* Wg  = (const float*)d_in[1];
    const float* bg  = (const float*)d_in[2];
    const float* Wc  = (const float*)d_in[3];
    const float* bc  = (const float*)d_in[4];
    const float* n1w = (const float*)d_in[5];
    const float* n2w = (const float*)d_in[6];
    const float* W1  = (const float*)d_in[7];
    const float* W3  = (const float*)d_in[8];
    const float* W2  = (const float*)d_in[9];
    float* out = (float*)d_out;

    __half *hin, *fin, *u, *at, *bt, *WgT, *WcT, *W1T, *W3T, *W2T;
    cudaGetSymbolAddress((void**)&hin, g_hin);
    cudaGetSymbolAddress((void**)&fin, g_fin);
    cudaGetSymbolAddress((void**)&at,  g_at);
    cudaGetSymbolAddress((void**)&bt,  g_bt);
    cudaGetSymbolAddress((void**)&u,   g_u);
    cudaGetSymbolAddress((void**)&WgT, g_WgT);
    cudaGetSymbolAddress((void**)&WcT, g_WcT);
    cudaGetSymbolAddress((void**)&W1T, g_W1T);
    cudaGetSymbolAddress((void**)&W3T, g_W3T);
    cudaGetSymbolAddress((void**)&W2T, g_W2T);

    cudaFuncSetAttribute(gemm_dual<M_GATES>, cudaFuncAttributeMaxDynamicSharedMemorySize, DSMEM);
    cudaFuncSetAttribute(gemm_dual<M_FF>,    cudaFuncAttributeMaxDynamicSharedMemorySize, DSMEM);
    cudaFuncSetAttribute(gemm_res,           cudaFuncAttributeMaxDynamicSharedMemorySize, SSMEM);
    cudaFuncSetAttribute(fuse_res_norm,      cudaFuncAttributeMaxDynamicSharedMemorySize, FRSMEM);

    // 0+1) rmsnorm1 + all weight transposes in ONE launch
    prep_kernel<<<MTOK + 14336, 256>>>(x, n1w, hin,
                                       Wg, Wc, W1, W3, W2,
                                       WgT, WcT, W1T, W3T, W2T);

    // 2) dual gates GEMM -> at = sigmoid(.), bt = (1-g)*tanh(.) in [b,d,t] fp16
    gemm_dual<M_GATES><<<dim3(DMODEL/BN, MTOK/BM), 512, DSMEM>>>(
        hin, WgT, WcT, at, bt, nullptr, bg, bc, DMODEL);

    // 3) linear-recurrence scan along t (in place in bt, fp32 compute)
    scan_kernel<<<BATCH * DMODEL, 256>>>(at, bt);

    // 4+5) out = x + h; fin = rmsnorm(out, n2_w) (fused, 256 thr, 2 CTAs/SM)
    fuse_res_norm<<<dim3(SEQ/32, BATCH), 256, FRSMEM>>>(x, bt, n2w, out, fin);

    // 6) dual FF GEMM -> u = half(silu(fin@W1T) * (fin@W3T)), coalesced writes
    gemm_dual<M_FF><<<dim3(DFF/BN, MTOK/BM), 512, DSMEM>>>(
        fin, W1T, W3T, nullptr, nullptr, u, nullptr, nullptr, DMODEL);

    // 7) out = x2 + u@W2T (residual fused; BKK=64, 3 stages)
    gemm_res<<<dim3(DMODEL/BN, MTOK/BM), 256, SSMEM>>>(u, W2T, out, DFF, DMODEL);
}

// round 15
// speedup vs baseline: 1.0878x; 1.0878x over previous
#include <cuda_runtime.h>
#include <cuda_fp16.h>
#include <math.h>
#include <stdint.h>

#define BATCH 4
#define SEQ   4096
#define DMODEL 1024
#define DFF   4096
#define MTOK  (BATCH*SEQ)

// ---- dual-B kernel: 512 threads, BKK=64, 4 stages (R13 config) ----
#define BM 128
#define BN 128
#define DKK 64
#define HSTR_D 72                                    // 64 + 8 pad halfs
#define DSTAGES 4
#define DSTAGE_HALFS ((BM + 2*BN) * HSTR_D)          // 27648 halfs = 55296 B
#define DSMEM (DSTAGES * DSTAGE_HALFS * 2)           // 221184

// ---- single-B (W2): 256 threads, BKK=32, 4 stages, 2 CTAs/SM (R13 cfg) ----
#define SKK 32
#define HSTR_S 40
#define SSTAGES 4
#define SSTAGE_HALFS ((BM + BN) * HSTR_S)            // 10240 halfs = 20480 B
#define SSMEM (SSTAGES * SSTAGE_HALFS * 2)           // 81920

#define M_GATES 0
#define M_FF    1

// fused residual+norm kernel: fp16 slab, 256 threads, 2 CTAs/SM
#define FR_HSTR 1026
#define FRSMEM (32 * FR_HSTR * 2)                    // 65664

// ------------------------- scratch -----------------------------------------
__device__ __half g_hin[MTOK*DMODEL];                // rmsnorm1 out; REUSED as x2 fp16
__device__ __half g_fin[MTOK*DMODEL];
__device__ __half g_at [BATCH*DMODEL*SEQ];           // gates, fp16 [b,d,t]
__device__ __half g_bt [BATCH*DMODEL*SEQ];           // (1-g)*c -> h, fp16 [b,d,t]
__device__ __half g_u  [(size_t)MTOK*DFF];
__device__ __half g_WgT[DMODEL*DMODEL];
__device__ __half g_WcT[DMODEL*DMODEL];
__device__ __half g_W1T[(size_t)DFF*DMODEL];
__device__ __half g_W3T[(size_t)DFF*DMODEL];
__device__ __half g_W2T[(size_t)DMODEL*DFF];

// ------------------------- helpers -----------------------------------------
__device__ __forceinline__ uint32_t smem_u32(const void* p) {
    uint32_t a;
    asm("{ .reg .u64 t; cvta.to.shared.u64 t, %1; cvt.u32.u64 %0, t; }"
        : "=r"(a) : "l"(p));
    return a;
}
#define CPA16(dst, src) \
    asm volatile("cp.async.cg.shared.global [%0], [%1], 16;" :: "r"(dst), "l"(src))
#define CPA_COMMIT() asm volatile("cp.async.commit_group;" ::: "memory")
#define CPA_WAITG(n) asm volatile("cp.async.wait_group %0;" :: "n"(n) : "memory")

__device__ __forceinline__ void hmma(float c[4], const uint32_t a[4], const uint32_t b[2]) {
    asm volatile(
        "mma.sync.aligned.m16n8k16.row.col.f32.f16.f16.f32 "
        "{%0,%1,%2,%3},{%4,%5,%6,%7},{%8,%9},{%0,%1,%2,%3};"
        : "+f"(c[0]), "+f"(c[1]), "+f"(c[2]), "+f"(c[3])
        : "r"(a[0]), "r"(a[1]), "r"(a[2]), "r"(a[3]), "r"(b[0]), "r"(b[1]));
}
__device__ __forceinline__ void ldsm4(uint32_t& r0, uint32_t& r1, uint32_t& r2,
                                      uint32_t& r3, uint32_t addr) {
    asm volatile("ldmatrix.sync.aligned.m8n8.x4.shared.b16 {%0,%1,%2,%3}, [%4];"
                 : "=r"(r0), "=r"(r1), "=r"(r2), "=r"(r3) : "r"(addr));
}
__device__ __forceinline__ int a_lm_off(int lane, int stride) {
    return (lane & 15) * stride + 8 * (lane >> 4);
}
__device__ __forceinline__ int b_lm_off(int lane, int stride) {
    return ((lane & 7) + 8 * (lane >> 4)) * stride + 8 * ((lane >> 3) & 1);
}

// ------------------------- dual-B fp16 GEMM (512 thr, 4 stages, R13) -------
template<int MODE>
__global__ __launch_bounds__(512, 1) void gemm_dual(
    const __half* __restrict__ A, const __half* __restrict__ B1T,
    const __half* __restrict__ B2T,
    __half* __restrict__ O1, __half* __restrict__ O2, __half* __restrict__ OU,
    const float* __restrict__ bias1, const float* __restrict__ bias2,
    int K)
{
    extern __shared__ __half smh[];
    const uint32_t sbase = smem_u32(smh);
    const int tid = threadIdx.x, lane = tid & 31, wid = tid >> 5;
    const int wm = wid & 3, wn = wid >> 2;     // 4x4 warps, 32x32 tile each
    const int m0 = blockIdx.y * BM, n0 = blockIdx.x * BN;
    const int NK = K / DKK;

    const int aoff = a_lm_off(lane, HSTR_D);
    const int boff = b_lm_off(lane, HSTR_D);

    float acc1[2][4][4] = {};
    float acc2[2][4][4] = {};

    #define DLOAD(stage, ktile)                                                   \
    {                                                                             \
        uint32_t base = sbase + (stage) * DSTAGE_HALFS * 2;                       \
        long koff = (long)(ktile) * DKK;                                          \
        _Pragma("unroll")                                                         \
        for (int i = 0; i < 6; i++) {                                             \
            int id = tid + i * 512;                                               \
            int row = id >> 3, ch = (id & 7) * 8;                                 \
            const __half* src;                                                    \
            if (row < 128)      src = A   + (long)(m0 + row)       * K + koff + ch; \
            else if (row < 256) src = B1T + (long)(n0 + row - 128) * K + koff + ch; \
            else                src = B2T + (long)(n0 + row - 256) * K + koff + ch; \
            CPA16(base + (row * HSTR_D + ch) * 2, src);                           \
        }                                                                         \
        CPA_COMMIT();                                                             \
    }

    #pragma unroll
    for (int ps = 0; ps < DSTAGES - 1; ps++) DLOAD(ps, ps);

    for (int kt = 0; kt < NK; kt++) {
        CPA_WAITG(DSTAGES - 2);
        __syncthreads();
        uint32_t stg = sbase + (kt % DSTAGES) * DSTAGE_HALFS * 2;
        uint32_t As  = stg;
        uint32_t B1s = stg + BM * HSTR_D * 2;
        uint32_t B2s = stg + (BM + BN) * HSTR_D * 2;
        #pragma unroll
        for (int ks = 0; ks < 4; ks++) {
            const int k0 = ks * 16;
            uint32_t af[2][4], bf1[4][2], bf2[4][2];
            #pragma unroll
            for (int i = 0; i < 2; i++) {
                uint32_t ad = As + ((wm*32 + i*16) * HSTR_D + k0 + aoff) * 2;
                ldsm4(af[i][0], af[i][1], af[i][2], af[i][3], ad);
            }
            #pragma unroll
            for (int jp = 0; jp < 2; jp++) {
                uint32_t bd1 = B1s + ((wn*32 + jp*16) * HSTR_D + k0 + boff) * 2;
                uint32_t bd2 = B2s + ((wn*32 + jp*16) * HSTR_D + k0 + boff) * 2;
                ldsm4(bf1[jp*2][0], bf1[jp*2][1], bf1[jp*2+1][0], bf1[jp*2+1][1], bd1);
                ldsm4(bf2[jp*2][0], bf2[jp*2][1], bf2[jp*2+1][0], bf2[jp*2+1][1], bd2);
            }
            #pragma unroll
            for (int i = 0; i < 2; i++)
                #pragma unroll
                for (int j = 0; j < 4; j++) {
                    hmma(acc1[i][j], af[i], bf1[j]);
                    hmma(acc2[i][j], af[i], bf2[j]);
                }
        }
        int nxt = kt + DSTAGES - 1;
        if (nxt < NK) DLOAD(nxt % DSTAGES, nxt)
        else CPA_COMMIT();
    }
    __syncthreads();   // smem reused for epilogue patches

    if (MODE == M_FF) {
        __half2* patch = (__half2*)smh + wid * (32 * 36);
        #pragma unroll
        for (int i = 0; i < 2; i++) {
            #pragma unroll
            for (int j = 0; j < 4; j++) {
                int r0 = i*16 + (lane>>2);
                int ch = j*4 + (lane&3);
                float a0 = acc1[i][j][0], a1 = acc1[i][j][1];
                float a2 = acc1[i][j][2], a3 = acc1[i][j][3];
                float v0 = a0 / (1.f + __expf(-a0)) * acc2[i][j][0];
                float v1 = a1 / (1.f + __expf(-a1)) * acc2[i][j][1];
                float v2 = a2 / (1.f + __expf(-a2)) * acc2[i][j][2];
                float v3 = a3 / (1.f + __expf(-a3)) * acc2[i][j][3];
                patch[r0*36 + ch]     = __floats2half2_rn(v0, v1);
                patch[(r0+8)*36 + ch] = __floats2half2_rn(v2, v3);
            }
        }
        __syncwarp();
        int tok0 = m0 + wm * 32;
        int cb = n0 + wn * 32;
        #pragma unroll
        for (int r2 = 0; r2 < 32; r2 += 2) {
            int rr = r2 + (lane >> 4);
            int cc = lane & 15;
            *(__half2*)(OU + (long)(tok0 + rr) * DFF + cb + cc*2) = patch[rr*36 + cc];
        }
    } else {
        float* patchG = (float*)smh + wid * 2 * (32 * 33);
        float* patchH = patchG + 32 * 33;
        #pragma unroll
        for (int i = 0; i < 2; i++) {
            #pragma unroll
            for (int j = 0; j < 4; j++) {
                int r0 = i*16 + (lane>>2);            // t-local 0..31
                int c0 = j*8 + 2*(lane&3);            // n-local 0..31
                int n  = n0 + wn*32 + c0;
                float b1a = bias1[n], b1b = bias1[n+1];
                float b2a = bias2[n], b2b = bias2[n+1];
                float g0 = 1.f / (1.f + __expf(-(acc1[i][j][0] + b1a)));
                float g1 = 1.f / (1.f + __expf(-(acc1[i][j][1] + b1b)));
                float g2 = 1.f / (1.f + __expf(-(acc1[i][j][2] + b1a)));
                float g3 = 1.f / (1.f + __expf(-(acc1[i][j][3] + b1b)));
                float h0 = (1.f - g0) * tanhf(acc2[i][j][0] + b2a);
                float h1 = (1.f - g1) * tanhf(acc2[i][j][1] + b2b);
                float h2 = (1.f - g2) * tanhf(acc2[i][j][2] + b2a);
                float h3 = (1.f - g3) * tanhf(acc2[i][j][3] + b2b);
                patchG[c0*33 + r0]       = g0;
                patchG[(c0+1)*33 + r0]   = g1;
                patchG[c0*33 + r0+8]     = g2;
                patchG[(c0+1)*33 + r0+8] = g3;
                patchH[c0*33 + r0]       = h0;
                patchH[(c0+1)*33 + r0]   = h1;
                patchH[c0*33 + r0+8]     = h2;
                patchH[(c0+1)*33 + r0+8] = h3;
            }
        }
        __syncwarp();
        int tokb = m0 + wm * 32;
        int b = tokb >> 12, tb = tokb & 4095;
        #pragma unroll 4
        for (int r = 0; r < 32; r++) {
            int n = n0 + wn*32 + r;
            long off = ((long)(b * DMODEL + n)) * SEQ + tb + lane;
            O1[off] = __float2half_rn(patchG[r*33 + lane]);
            O2[off] = __float2half_rn(patchH[r*33 + lane]);
        }
    }
    #undef DLOAD
}

// --------- single-B fp16 GEMM: O = X2(fp16) + A@BT^T (final output) --------
__global__ __launch_bounds__(256, 2) void gemm_res(
    const __half* __restrict__ A, const __half* __restrict__ BT,
    const __half* __restrict__ X2, float* __restrict__ O, int K, int ldo)
{
    extern __shared__ __half smh[];
    const uint32_t sbase = smem_u32(smh);
    const int tid = threadIdx.x, lane = tid & 31, wid = tid >> 5;
    const int wm = wid & 1, wn = wid >> 1;
    const int m0 = blockIdx.y * BM, n0 = blockIdx.x * BN;
    const int NK = K / SKK;

    const int aoff = a_lm_off(lane, HSTR_S);
    const int boff = b_lm_off(lane, HSTR_S);

    float acc[4][4][4] = {};

    #define SLOAD(stage, ktile)                                                   \
    {                                                                             \
        uint32_t base = sbase + (stage) * SSTAGE_HALFS * 2;                       \
        long koff = (long)(ktile) * SKK;                                          \
        _Pragma("unroll")                                                         \
        for (int i = 0; i < 4; i++) {                                             \
            int id = tid + i * 256;                                               \
            int row = id >> 2, ch = (id & 3) * 8;                                 \
            const __half* src;                                                    \
            if (row < 128) src = A  + (long)(m0 + row)       * K + koff + ch;     \
            else           src = BT + (long)(n0 + row - 128) * K + koff + ch;     \
            CPA16(base + (row * HSTR_S + ch) * 2, src);                           \
        }                                                                         \
        CPA_COMMIT();                                                             \
    }

    #pragma unroll
    for (int ps = 0; ps < SSTAGES - 1; ps++) SLOAD(ps, ps);

    for (int kt = 0; kt < NK; kt++) {
        CPA_WAITG(SSTAGES - 2);
        __syncthreads();
        uint32_t stg = sbase + (kt % SSTAGES) * SSTAGE_HALFS * 2;
        uint32_t As = stg;
        uint32_t Bs = stg + BM * HSTR_S * 2;
        #pragma unroll
        for (int ks = 0; ks < 2; ks++) {
            const int k0 = ks * 16;
            uint32_t af[4][4], bf[4][2];
            #pragma unroll
            for (int i = 0; i < 4; i++) {
                uint32_t ad = As + ((wm*64 + i*16) * HSTR_S + k0 + aoff) * 2;
                ldsm4(af[i][0], af[i][1], af[i][2], af[i][3], ad);
            }
            #pragma unroll
            for (int jp = 0; jp < 2; jp++) {
                uint32_t bd = Bs + ((wn*32 + jp*16) * HSTR_S + k0 + boff) * 2;
                ldsm4(bf[jp*2][0], bf[jp*2][1], bf[jp*2+1][0], bf[jp*2+1][1], bd);
            }
            #pragma unroll
            for (int i = 0; i < 4; i++)
                #pragma unroll
                for (int j = 0; j < 4; j++)
                    hmma(acc[i][j], af[i], bf[j]);
        }
        int nxt = kt + SSTAGES - 1;
        if (nxt < NK) SLOAD(nxt % SSTAGES, nxt)
        else CPA_COMMIT();
    }

    #pragma unroll
    for (int i = 0; i < 4; i++) {
        #pragma unroll
        for (int j = 0; j < 4; j++) {
            int r0 = m0 + wm*64 + i*16 + (lane>>2);
            int c0 = n0 + wn*32 + j*8 + 2*(lane&3);
            long o0 = (long)r0 * ldo + c0;
            long o1 = o0 + (long)8 * ldo;
            float2 p0 = __half22float2(*(const __half2*)(X2 + o0));
            float2 p1 = __half22float2(*(const __half2*)(X2 + o1));
            *(float2*)(O + o0) = make_float2(acc[i][j][0] + p0.x, acc[i][j][1] + p0.y);
            *(float2*)(O + o1) = make_float2(acc[i][j][2] + p1.x, acc[i][j][3] + p1.y);
        }
    }
    #undef SLOAD
}

// ------ prep: rmsnorm (blocks < MTOK) + all weight transposes (rest) -------
__global__ __launch_bounds__(256) void prep_kernel(
    const float* __restrict__ x, const float* __restrict__ w, __half* __restrict__ y,
    const float* __restrict__ Wg, const float* __restrict__ Wc,
    const float* __restrict__ W1, const float* __restrict__ W3,
    const float* __restrict__ W2,
    __half* __restrict__ WgT, __half* __restrict__ WcT,
    __half* __restrict__ W1T, __half* __restrict__ W3T,
    __half* __restrict__ W2T)
{
    __shared__ float sred[8];
    __shared__ float tile[32][33];
    int bid = blockIdx.x, tid = threadIdx.x;

    if (bid >= MTOK) {
        int s = bid - MTOK;                    // 0..14335
        const float* W; __half* WT; int Kw, Nw, tt;
        if (s < 1024)       { W = Wg; WT = WgT; Kw = DMODEL; Nw = DMODEL; tt = s; }
        else if (s < 2048)  { W = Wc; WT = WcT; Kw = DMODEL; Nw = DMODEL; tt = s - 1024; }
        else if (s < 6144)  { W = W1; WT = W1T; Kw = DMODEL; Nw = DFF;    tt = s - 2048; }
        else if (s < 10240) { W = W3; WT = W3T; Kw = DMODEL; Nw = DFF;    tt = s - 6144; }
        else                { W = W2; WT = W2T; Kw = DFF;    Nw = DMODEL; tt = s - 10240; }
        int ntx = Nw >> 5;
        int n0 = (tt % ntx) * 32, k0 = (tt / ntx) * 32;
        int tx = tid & 31, ty = tid >> 5;
        #pragma unroll
        for (int i = 0; i < 4; i++)
            tile[ty + 8*i][tx] = W[(long)(k0 + ty + 8*i) * Nw + n0 + tx];
        __syncthreads();
        #pragma unroll
        for (int i = 0; i < 4; i++)
            WT[(long)(n0 + ty + 8*i) * Kw + k0 + tx] =
                __float2half_rn(tile[tx][ty + 8*i]);
        return;
    }

    float4 v = ((const float4*)(x + (long)bid * DMODEL))[tid];
    float ss = v.x*v.x + v.y*v.y + v.z*v.z + v.w*v.w;
    #pragma unroll
    for (int o = 16; o; o >>= 1) ss += __shfl_xor_sync(0xffffffffu, ss, o);
    if ((tid & 31) == 0) sred[tid >> 5] = ss;
    __syncthreads();
    if (tid < 8) {
        float t = sred[tid];
        #pragma unroll
        for (int o = 4; o; o >>= 1) t += __shfl_xor_sync(0xffu, t, o);
        if (tid == 0) sred[0] = t;
    }
    __syncthreads();
    float scale = rsqrtf(sred[0] * (1.0f / DMODEL) + 1e-6f);
    float4 wv = ((const float4*)w)[tid];
    __half2 h01 = __floats2half2_rn(v.x*scale*wv.x, v.y*scale*wv.y);
    __half2 h23 = __floats2half2_rn(v.z*scale*wv.z, v.w*scale*wv.w);
    __half2* yp = (__half2*)(y + (long)bid * DMODEL) + tid * 2;
    yp[0] = h01; yp[1] = h23;
}

// ---- fused: x2 = x + h^T; x2h = half(x2); fin = half(rmsnorm(x2)*w) --------
__global__ __launch_bounds__(256) void fuse_res_norm(
    const float* __restrict__ x, const __half* __restrict__ ht,
    const float* __restrict__ w,
    __half* __restrict__ x2h, __half* __restrict__ fin)
{
    extern __shared__ __half hslab[];          // [32][FR_HSTR]
    const int t0 = blockIdx.x * 32, b = blockIdx.y;
    const int tid = threadIdx.x, lane = tid & 31, wid = tid >> 5;

    for (int g = 0; g < 4; g++) {
        for (int dc = 0; dc < 32; dc++) {
            int d = g * 256 + dc * 8 + wid;
            const __half* src = ht + ((long)(b * DMODEL + d)) * SEQ + t0;
            hslab[lane * FR_HSTR + d] = src[lane];
        }
    }
    __syncthreads();

    #pragma unroll
    for (int k = 0; k < 4; k++) {
        int tt = wid * 4 + k;
        int tok = b * SEQ + t0 + tt;
        const __half* row = hslab + tt * FR_HSTR;
        const float* xr = x + (long)tok * DMODEL;
        float ss = 0.f;
        float vals[32];
        #pragma unroll
        for (int q = 0; q < 32; q++) {
            float v = xr[q * 32 + lane] + __half2float(row[q * 32 + lane]);
            vals[q] = v;
            ss += v * v;
        }
        #pragma unroll
        for (int o = 16; o; o >>= 1) ss += __shfl_xor_sync(0xffffffffu, ss, o);
        float scale = rsqrtf(ss * (1.0f / DMODEL) + 1e-6f);
        __half* xrow2 = x2h + (long)tok * DMODEL;
        __half* frow  = fin + (long)tok * DMODEL;
        #pragma unroll
        for (int q = 0; q < 32; q++) {
            int d = q * 32 + lane;
            xrow2[d] = __float2half_rn(vals[q]);
            frow[d]  = __float2half_rn(vals[q] * scale * w[d]);
        }
    }
}

// ------------------- scan over t (per (b,d) row, uint4 fp16 I/O) -----------
__global__ __launch_bounds__(256) void scan_kernel(
    const __half* __restrict__ at, __half* __restrict__ bt)
{
    long base = (long)blockIdx.x * SEQ;
    int tid = threadIdx.x;
    float la[16], lb[16];
    const uint4* ap = (const uint4*)(at + base) + tid * 2;
    uint4*       bp = (uint4*)(bt + base) + tid * 2;
    uint4 va[2] = { ap[0], ap[1] };
    uint4 vb[2] = { bp[0], bp[1] };
    #pragma unroll
    for (int q = 0; q < 8; q++) {
        float2 fa = __half22float2(((const __half2*)va)[q]);
        float2 fb = __half22float2(((const __half2*)vb)[q]);
        la[2*q] = fa.x; la[2*q+1] = fa.y;
        lb[2*q] = fb.x; lb[2*q+1] = fb.y;
    }
    float A = 1.f, Bc = 0.f;
    #pragma unroll
    for (int j = 0; j < 16; j++) { Bc = la[j] * Bc + lb[j]; A *= la[j]; }
    __shared__ float sA[256], sB[256];
    sA[tid] = A; sB[tid] = Bc;
    __syncthreads();
    #pragma unroll
    for (int off = 1; off < 256; off <<= 1) {
        float pA = 1.f, pB = 0.f;
        if (tid >= off) { pA = sA[tid - off]; pB = sB[tid - off]; }
        float cA = sA[tid], cB = sB[tid];
        __syncthreads();
        sA[tid] = pA * cA;
        sB[tid] = cA * pB + cB;
        __syncthreads();
    }
    float carry = (tid > 0) ? sB[tid - 1] : 0.f;
    #pragma unroll
    for (int j = 0; j < 16; j++) { carry = la[j] * carry + lb[j]; lb[j] = carry; }
    #pragma unroll
    for (int q = 0; q < 8; q++)
        ((__half2*)vb)[q] = __floats2half2_rn(lb[2*q], lb[2*q+1]);
    bp[0] = vb[0]; bp[1] = vb[1];
}

// ----------------------------------------------------------------------------
extern "C" void kernel_launch(void* const* d_in, const int* in_sizes, int n_in,
                              void* d_out, int out_size)
{
    const float* x   = (const float*)d_in[0];
    const float* Wg  = (const float*)d_in[1];
    const float* bg  = (const float*)d_in[2];
    const float* Wc  = (const float*)d_in[3];
    const float* bc  = (const float*)d_in[4];
    const float* n1w = (const float*)d_in[5];
    const float* n2w = (const float*)d_in[6];
    const float* W1  = (const float*)d_in[7];
    const float* W3  = (const float*)d_in[8];
    const float* W2  = (const float*)d_in[9];
    float* out = (float*)d_out;

    __half *hin, *fin, *u, *at, *bt, *WgT, *WcT, *W1T, *W3T, *W2T;
    cudaGetSymbolAddress((void**)&hin, g_hin);
    cudaGetSymbolAddress((void**)&fin, g_fin);
    cudaGetSymbolAddress((void**)&at,  g_at);
    cudaGetSymbolAddress((void**)&bt,  g_bt);
    cudaGetSymbolAddress((void**)&u,   g_u);
    cudaGetSymbolAddress((void**)&WgT, g_WgT);
    cudaGetSymbolAddress((void**)&WcT, g_WcT);
    cudaGetSymbolAddress((void**)&W1T, g_W1T);
    cudaGetSymbolAddress((void**)&W3T, g_W3T);
    cudaGetSymbolAddress((void**)&W2T, g_W2T);

    cudaFuncSetAttribute(gemm_dual<M_GATES>, cudaFuncAttributeMaxDynamicSharedMemorySize, DSMEM);
    cudaFuncSetAttribute(gemm_dual<M_FF>,    cudaFuncAttributeMaxDynamicSharedMemorySize, DSMEM);
    cudaFuncSetAttribute(gemm_res,           cudaFuncAttributeMaxDynamicSharedMemorySize, SSMEM);
    cudaFuncSetAttribute(fuse_res_norm,      cudaFuncAttributeMaxDynamicSharedMemorySize, FRSMEM);

    // 0+1) rmsnorm1 + all weight transposes in ONE launch
    prep_kernel<<<MTOK + 14336, 256>>>(x, n1w, hin,
                                       Wg, Wc, W1, W3, W2,
                                       WgT, WcT, W1T, W3T, W2T);

    // 2) dual gates GEMM -> at = sigmoid(.), bt = (1-g)*tanh(.) in [b,d,t] fp16
    gemm_dual<M_GATES><<<dim3(DMODEL/BN, MTOK/BM), 512, DSMEM>>>(
        hin, WgT, WcT, at, bt, nullptr, bg, bc, DMODEL);

    // 3) linear-recurrence scan along t (in place in bt, fp32 compute)
    scan_kernel<<<BATCH * DMODEL, 256>>>(at, bt);

    // 4+5) x2h = half(x + h) (hin reused); fin = half(rmsnorm(x2)*n2w)
    fuse_res_norm<<<dim3(SEQ/32, BATCH), 256, FRSMEM>>>(x, bt, n2w, hin, fin);

    // 6) dual FF GEMM -> u = half(silu(fin@W1T) * (fin@W3T)), coalesced writes
    gemm_dual<M_FF><<<dim3(DFF/BN, MTOK/BM), 512, DSMEM>>>(
        fin, W1T, W3T, nullptr, nullptr, u, nullptr, nullptr, DMODEL);

    // 7) out = x2h + u@W2T (fp16 residual read; final f32 output)
    gemm_res<<<dim3(DMODEL/BN, MTOK/BM), 256, SSMEM>>>(u, W2T, hin, out, DFF, DMODEL);
}

// round 16
// speedup vs baseline: 1.0957x; 1.0072x over previous
#include <cuda_runtime.h>
#include <cuda_fp16.h>
#include <math.h>
#include <stdint.h>

#define BATCH 4
#define SEQ   4096
#define DMODEL 1024
#define DFF   4096
#define MTOK  (BATCH*SEQ)

// ---- dual-B kernel: 512 threads, BKK=64, 4 stages ----
#define BM 128
#define BN 128
#define DKK 64
#define HSTR_D 72                                    // 64 + 8 pad halfs
#define DSTAGES 4
#define DSTAGE_HALFS ((BM + 2*BN) * HSTR_D)          // 27648 halfs = 55296 B
#define DSMEM (DSTAGES * DSTAGE_HALFS * 2)           // 221184

// ---- single-B (W2): 256 threads, BKK=32, 4 stages, 2 CTAs/SM ----
#define SKK 32
#define HSTR_S 40
#define SSTAGES 4
#define SSTAGE_HALFS ((BM + BN) * HSTR_S)            // 10240 halfs = 20480 B
#define SSMEM (SSTAGES * SSTAGE_HALFS * 2)           // 81920

#define M_GATES 0
#define M_FF    1

// fused residual+norm kernel: fp16 slab, 256 threads, 2 CTAs/SM
#define FR_HSTR 1026
#define FRSMEM (32 * FR_HSTR * 2)                    // 65664

// ------------------------- scratch -----------------------------------------
__device__ __half g_hin[MTOK*DMODEL];                // rmsnorm1 out; REUSED as x2 fp16
__device__ __half g_fin[MTOK*DMODEL];
__device__ __half g_at [BATCH*DMODEL*SEQ];           // gates, fp16 [b,d,t]
__device__ __half g_bt [BATCH*DMODEL*SEQ];           // (1-g)*c -> h, fp16 [b,d,t]
__device__ __half g_u  [(size_t)MTOK*DFF];
__device__ __half g_WgT[DMODEL*DMODEL];
__device__ __half g_WcT[DMODEL*DMODEL];
__device__ __half g_W1T[(size_t)DFF*DMODEL];
__device__ __half g_W3T[(size_t)DFF*DMODEL];
__device__ __half g_W2T[(size_t)DMODEL*DFF];

// ------------------------- helpers -----------------------------------------
__device__ __forceinline__ uint32_t smem_u32(const void* p) {
    uint32_t a;
    asm("{ .reg .u64 t; cvta.to.shared.u64 t, %1; cvt.u32.u64 %0, t; }"
        : "=r"(a) : "l"(p));
    return a;
}
#define CPA16(dst, src) \
    asm volatile("cp.async.cg.shared.global [%0], [%1], 16;" :: "r"(dst), "l"(src))
#define CPA_COMMIT() asm volatile("cp.async.commit_group;" ::: "memory")
#define CPA_WAITG(n) asm volatile("cp.async.wait_group %0;" :: "n"(n) : "memory")

__device__ __forceinline__ void hmma(float c[4], const uint32_t a[4], const uint32_t b[2]) {
    asm volatile(
        "mma.sync.aligned.m16n8k16.row.col.f32.f16.f16.f32 "
        "{%0,%1,%2,%3},{%4,%5,%6,%7},{%8,%9},{%0,%1,%2,%3};"
        : "+f"(c[0]), "+f"(c[1]), "+f"(c[2]), "+f"(c[3])
        : "r"(a[0]), "r"(a[1]), "r"(a[2]), "r"(a[3]), "r"(b[0]), "r"(b[1]));
}
__device__ __forceinline__ void ldsm4(uint32_t& r0, uint32_t& r1, uint32_t& r2,
                                      uint32_t& r3, uint32_t addr) {
    asm volatile("ldmatrix.sync.aligned.m8n8.x4.shared.b16 {%0,%1,%2,%3}, [%4];"
                 : "=r"(r0), "=r"(r1), "=r"(r2), "=r"(r3) : "r"(addr));
}
__device__ __forceinline__ int a_lm_off(int lane, int stride) {
    return (lane & 15) * stride + 8 * (lane >> 4);
}
__device__ __forceinline__ int b_lm_off(int lane, int stride) {
    return ((lane & 7) + 8 * (lane >> 4)) * stride + 8 * ((lane >> 3) & 1);
}

// ------------------------- dual-B fp16 GEMM (512 thr, 4 stages) ------------
// Next-stage cp.async spread across ks iterations (2 per ks, commit at ks=2).
template<int MODE>
__global__ __launch_bounds__(512, 1) void gemm_dual(
    const __half* __restrict__ A, const __half* __restrict__ B1T,
    const __half* __restrict__ B2T,
    __half* __restrict__ O1, __half* __restrict__ O2, __half* __restrict__ OU,
    const float* __restrict__ bias1, const float* __restrict__ bias2,
    int K)
{
    extern __shared__ __half smh[];
    const uint32_t sbase = smem_u32(smh);
    const int tid = threadIdx.x, lane = tid & 31, wid = tid >> 5;
    const int wm = wid & 3, wn = wid >> 2;     // 4x4 warps, 32x32 tile each
    const int m0 = blockIdx.y * BM, n0 = blockIdx.x * BN;
    const int NK = K / DKK;

    const int aoff = a_lm_off(lane, HSTR_D);
    const int boff = b_lm_off(lane, HSTR_D);

    float acc1[2][4][4] = {};
    float acc2[2][4][4] = {};

    // issue cp.async for iterations [p0, p1) of the 6 per-thread chunks
    #define DPART(stage, ktile, p0, p1)                                           \
    {                                                                             \
        uint32_t base = sbase + (stage) * DSTAGE_HALFS * 2;                       \
        long koff = (long)(ktile) * DKK;                                          \
        _Pragma("unroll")                                                         \
        for (int i = (p0); i < (p1); i++) {                                       \
            int id = tid + i * 512;                                               \
            int row = id >> 3, ch = (id & 7) * 8;                                 \
            const __half* src;                                                    \
            if (row < 128)      src = A   + (long)(m0 + row)       * K + koff + ch; \
            else if (row < 256) src = B1T + (long)(n0 + row - 128) * K + koff + ch; \
            else                src = B2T + (long)(n0 + row - 256) * K + koff + ch; \
            CPA16(base + (row * HSTR_D + ch) * 2, src);                           \
        }                                                                         \
    }

    #pragma unroll
    for (int ps = 0; ps < DSTAGES - 1; ps++) { DPART(ps, ps, 0, 6); CPA_COMMIT(); }

    for (int kt = 0; kt < NK; kt++) {
        CPA_WAITG(DSTAGES - 2);
        __syncthreads();
        const int nxt = kt + DSTAGES - 1;
        const int nst = nxt % DSTAGES;
        const bool more = (nxt < NK);

        uint32_t stg = sbase + (kt % DSTAGES) * DSTAGE_HALFS * 2;
        uint32_t As  = stg;
        uint32_t B1s = stg + BM * HSTR_D * 2;
        uint32_t B2s = stg + (BM + BN) * HSTR_D * 2;
        #pragma unroll
        for (int ks = 0; ks < 4; ks++) {
            // spread next-stage loads: 2 chunks before ks=0,1,2
            if (ks < 3 && more) DPART(nst, nxt, ks * 2, ks * 2 + 2);
            if (ks == 2) CPA_COMMIT();   // all 6 chunks issued (or empty group)

            const int k0 = ks * 16;
            uint32_t af[2][4], bf1[4][2], bf2[4][2];
            #pragma unroll
            for (int i = 0; i < 2; i++) {
                uint32_t ad = As + ((wm*32 + i*16) * HSTR_D + k0 + aoff) * 2;
                ldsm4(af[i][0], af[i][1], af[i][2], af[i][3], ad);
            }
            #pragma unroll
            for (int jp = 0; jp < 2; jp++) {
                uint32_t bd1 = B1s + ((wn*32 + jp*16) * HSTR_D + k0 + boff) * 2;
                uint32_t bd2 = B2s + ((wn*32 + jp*16) * HSTR_D + k0 + boff) * 2;
                ldsm4(bf1[jp*2][0], bf1[jp*2][1], bf1[jp*2+1][0], bf1[jp*2+1][1], bd1);
                ldsm4(bf2[jp*2][0], bf2[jp*2][1], bf2[jp*2+1][0], bf2[jp*2+1][1], bd2);
            }
            #pragma unroll
            for (int i = 0; i < 2; i++)
                #pragma unroll
                for (int j = 0; j < 4; j++) {
                    hmma(acc1[i][j], af[i], bf1[j]);
                    hmma(acc2[i][j], af[i], bf2[j]);
                }
        }
    }
    __syncthreads();   // smem reused for epilogue patches

    if (MODE == M_FF) {
        __half2* patch = (__half2*)smh + wid * (32 * 36);
        #pragma unroll
        for (int i = 0; i < 2; i++) {
            #pragma unroll
            for (int j = 0; j < 4; j++) {
                int r0 = i*16 + (lane>>2);
                int ch = j*4 + (lane&3);
                float a0 = acc1[i][j][0], a1 = acc1[i][j][1];
                float a2 = acc1[i][j][2], a3 = acc1[i][j][3];
                float v0 = a0 / (1.f + __expf(-a0)) * acc2[i][j][0];
                float v1 = a1 / (1.f + __expf(-a1)) * acc2[i][j][1];
                float v2 = a2 / (1.f + __expf(-a2)) * acc2[i][j][2];
                float v3 = a3 / (1.f + __expf(-a3)) * acc2[i][j][3];
                patch[r0*36 + ch]     = __floats2half2_rn(v0, v1);
                patch[(r0+8)*36 + ch] = __floats2half2_rn(v2, v3);
            }
        }
        __syncwarp();
        int tok0 = m0 + wm * 32;
        int cb = n0 + wn * 32;
        #pragma unroll
        for (int r2 = 0; r2 < 32; r2 += 2) {
            int rr = r2 + (lane >> 4);
            int cc = lane & 15;
            *(__half2*)(OU + (long)(tok0 + rr) * DFF + cb + cc*2) = patch[rr*36 + cc];
        }
    } else {
        float* patchG = (float*)smh + wid * 2 * (32 * 33);
        float* patchH = patchG + 32 * 33;
        #pragma unroll
        for (int i = 0; i < 2; i++) {
            #pragma unroll
            for (int j = 0; j < 4; j++) {
                int r0 = i*16 + (lane>>2);            // t-local 0..31
                int c0 = j*8 + 2*(lane&3);            // n-local 0..31
                int n  = n0 + wn*32 + c0;
                float b1a = bias1[n], b1b = bias1[n+1];
                float b2a = bias2[n], b2b = bias2[n+1];
                float g0 = 1.f / (1.f + __expf(-(acc1[i][j][0] + b1a)));
                float g1 = 1.f / (1.f + __expf(-(acc1[i][j][1] + b1b)));
                float g2 = 1.f / (1.f + __expf(-(acc1[i][j][2] + b1a)));
                float g3 = 1.f / (1.f + __expf(-(acc1[i][j][3] + b1b)));
                float h0 = (1.f - g0) * tanhf(acc2[i][j][0] + b2a);
                float h1 = (1.f - g1) * tanhf(acc2[i][j][1] + b2b);
                float h2 = (1.f - g2) * tanhf(acc2[i][j][2] + b2a);
                float h3 = (1.f - g3) * tanhf(acc2[i][j][3] + b2b);
                patchG[c0*33 + r0]       = g0;
                patchG[(c0+1)*33 + r0]   = g1;
                patchG[c0*33 + r0+8]     = g2;
                patchG[(c0+1)*33 + r0+8] = g3;
                patchH[c0*33 + r0]       = h0;
                patchH[(c0+1)*33 + r0]   = h1;
                patchH[c0*33 + r0+8]     = h2;
                patchH[(c0+1)*33 + r0+8] = h3;
            }
        }
        __syncwarp();
        int tokb = m0 + wm * 32;
        int b = tokb >> 12, tb = tokb & 4095;
        #pragma unroll 4
        for (int r = 0; r < 32; r++) {
            int n = n0 + wn*32 + r;
            long off = ((long)(b * DMODEL + n)) * SEQ + tb + lane;
            O1[off] = __float2half_rn(patchG[r*33 + lane]);
            O2[off] = __float2half_rn(patchH[r*33 + lane]);
        }
    }
    #undef DPART
}

// --------- single-B fp16 GEMM: O = X2(fp16) + A@BT^T (final output) --------
__global__ __launch_bounds__(256, 2) void gemm_res(
    const __half* __restrict__ A, const __half* __restrict__ BT,
    const __half* __restrict__ X2, float* __restrict__ O, int K, int ldo)
{
    extern __shared__ __half smh[];
    const uint32_t sbase = smem_u32(smh);
    const int tid = threadIdx.x, lane = tid & 31, wid = tid >> 5;
    const int wm = wid & 1, wn = wid >> 1;
    const int m0 = blockIdx.y * BM, n0 = blockIdx.x * BN;
    const int NK = K / SKK;

    const int aoff = a_lm_off(lane, HSTR_S);
    const int boff = b_lm_off(lane, HSTR_S);

    float acc[4][4][4] = {};

    #define SLOAD(stage, ktile)                                                   \
    {                                                                             \
        uint32_t base = sbase + (stage) * SSTAGE_HALFS * 2;                       \
        long koff = (long)(ktile) * SKK;                                          \
        _Pragma("unroll")                                                         \
        for (int i = 0; i < 4; i++) {                                             \
            int id = tid + i * 256;                                               \
            int row = id >> 2, ch = (id & 3) * 8;                                 \
            const __half* src;                                                    \
            if (row < 128) src = A  + (long)(m0 + row)       * K + koff + ch;     \
            else           src = BT + (long)(n0 + row - 128) * K + koff + ch;     \
            CPA16(base + (row * HSTR_S + ch) * 2, src);                           \
        }                                                                         \
        CPA_COMMIT();                                                             \
    }

    #pragma unroll
    for (int ps = 0; ps < SSTAGES - 1; ps++) SLOAD(ps, ps);

    for (int kt = 0; kt < NK; kt++) {
        CPA_WAITG(SSTAGES - 2);
        __syncthreads();
        uint32_t stg = sbase + (kt % SSTAGES) * SSTAGE_HALFS * 2;
        uint32_t As = stg;
        uint32_t Bs = stg + BM * HSTR_S * 2;
        #pragma unroll
        for (int ks = 0; ks < 2; ks++) {
            const int k0 = ks * 16;
            uint32_t af[4][4], bf[4][2];
            #pragma unroll
            for (int i = 0; i < 4; i++) {
                uint32_t ad = As + ((wm*64 + i*16) * HSTR_S + k0 + aoff) * 2;
                ldsm4(af[i][0], af[i][1], af[i][2], af[i][3], ad);
            }
            #pragma unroll
            for (int jp = 0; jp < 2; jp++) {
                uint32_t bd = Bs + ((wn*32 + jp*16) * HSTR_S + k0 + boff) * 2;
                ldsm4(bf[jp*2][0], bf[jp*2][1], bf[jp*2+1][0], bf[jp*2+1][1], bd);
            }
            #pragma unroll
            for (int i = 0; i < 4; i++)
                #pragma unroll
                for (int j = 0; j < 4; j++)
                    hmma(acc[i][j], af[i], bf[j]);
        }
        int nxt = kt + SSTAGES - 1;
        if (nxt < NK) SLOAD(nxt % SSTAGES, nxt)
        else CPA_COMMIT();
    }

    #pragma unroll
    for (int i = 0; i < 4; i++) {
        #pragma unroll
        for (int j = 0; j < 4; j++) {
            int r0 = m0 + wm*64 + i*16 + (lane>>2);
            int c0 = n0 + wn*32 + j*8 + 2*(lane&3);
            long o0 = (long)r0 * ldo + c0;
            long o1 = o0 + (long)8 * ldo;
            float2 p0 = __half22float2(*(const __half2*)(X2 + o0));
            float2 p1 = __half22float2(*(const __half2*)(X2 + o1));
            *(float2*)(O + o0) = make_float2(acc[i][j][0] + p0.x, acc[i][j][1] + p0.y);
            *(float2*)(O + o1) = make_float2(acc[i][j][2] + p1.x, acc[i][j][3] + p1.y);
        }
    }
    #undef SLOAD
}

// ------ prep: rmsnorm (blocks < MTOK) + all weight transposes (rest) -------
__global__ __launch_bounds__(256) void prep_kernel(
    const float* __restrict__ x, const float* __restrict__ w, __half* __restrict__ y,
    const float* __restrict__ Wg, const float* __restrict__ Wc,
    const float* __restrict__ W1, const float* __restrict__ W3,
    const float* __restrict__ W2,
    __half* __restrict__ WgT, __half* __restrict__ WcT,
    __half* __restrict__ W1T, __half* __restrict__ W3T,
    __half* __restrict__ W2T)
{
    __shared__ float sred[8];
    __shared__ float tile[32][33];
    int bid = blockIdx.x, tid = threadIdx.x;

    if (bid >= MTOK) {
        int s = bid - MTOK;                    // 0..14335
        const float* W; __half* WT; int Kw, Nw, tt;
        if (s < 1024)       { W = Wg; WT = WgT; Kw = DMODEL; Nw = DMODEL; tt = s; }
        else if (s < 2048)  { W = Wc; WT = WcT; Kw = DMODEL; Nw = DMODEL; tt = s - 1024; }
        else if (s < 6144)  { W = W1; WT = W1T; Kw = DMODEL; Nw = DFF;    tt = s - 2048; }
        else if (s < 10240) { W = W3; WT = W3T; Kw = DMODEL; Nw = DFF;    tt = s - 6144; }
        else                { W = W2; WT = W2T; Kw = DFF;    Nw = DMODEL; tt = s - 10240; }
        int ntx = Nw >> 5;
        int n0 = (tt % ntx) * 32, k0 = (tt / ntx) * 32;
        int tx = tid & 31, ty = tid >> 5;
        #pragma unroll
        for (int i = 0; i < 4; i++)
            tile[ty + 8*i][tx] = W[(long)(k0 + ty + 8*i) * Nw + n0 + tx];
        __syncthreads();
        #pragma unroll
        for (int i = 0; i < 4; i++)
            WT[(long)(n0 + ty + 8*i) * Kw + k0 + tx] =
                __float2half_rn(tile[tx][ty + 8*i]);
        return;
    }

    float4 v = ((const float4*)(x + (long)bid * DMODEL))[tid];
    float ss = v.x*v.x + v.y*v.y + v.z*v.z + v.w*v.w;
    #pragma unroll
    for (int o = 16; o; o >>= 1) ss += __shfl_xor_sync(0xffffffffu, ss, o);
    if ((tid & 31) == 0) sred[tid >> 5] = ss;
    __syncthreads();
    if (tid < 8) {
        float t = sred[tid];
        #pragma unroll
        for (int o = 4; o; o >>= 1) t += __shfl_xor_sync(0xffu, t, o);
        if (tid == 0) sred[0] = t;
    }
    __syncthreads();
    float scale = rsqrtf(sred[0] * (1.0f / DMODEL) + 1e-6f);
    float4 wv = ((const float4*)w)[tid];
    __half2 h01 = __floats2half2_rn(v.x*scale*wv.x, v.y*scale*wv.y);
    __half2 h23 = __floats2half2_rn(v.z*scale*wv.z, v.w*scale*wv.w);
    __half2* yp = (__half2*)(y + (long)bid * DMODEL) + tid * 2;
    yp[0] = h01; yp[1] = h23;
}

// ---- fused: x2 = x + h^T; x2h = half(x2); fin = half(rmsnorm(x2)*w) --------
__global__ __launch_bounds__(256) void fuse_res_norm(
    const float* __restrict__ x, const __half* __restrict__ ht,
    const float* __restrict__ w,
    __half* __restrict__ x2h, __half* __restrict__ fin)
{
    extern __shared__ __half hslab[];          // [32][FR_HSTR]
    const int t0 = blockIdx.x * 32, b = blockIdx.y;
    const int tid = threadIdx.x, lane = tid & 31, wid = tid >> 5;

    for (int g = 0; g < 4; g++) {
        for (int dc = 0; dc < 32; dc++) {
            int d = g * 256 + dc * 8 + wid;
            const __half* src = ht + ((long)(b * DMODEL + d)) * SEQ + t0;
            hslab[lane * FR_HSTR + d] = src[lane];
        }
    }
    __syncthreads();

    #pragma unroll
    for (int k = 0; k < 4; k++) {
        int tt = wid * 4 + k;
        int tok = b * SEQ + t0 + tt;
        const __half* row = hslab + tt * FR_HSTR;
        const float* xr = x + (long)tok * DMODEL;
        float ss = 0.f;
        float vals[32];
        #pragma unroll
        for (int q = 0; q < 32; q++) {
            float v = xr[q * 32 + lane] + __half2float(row[q * 32 + lane]);
            vals[q] = v;
            ss += v * v;
        }
        #pragma unroll
        for (int o = 16; o; o >>= 1) ss += __shfl_xor_sync(0xffffffffu, ss, o);
        float scale = rsqrtf(ss * (1.0f / DMODEL) + 1e-6f);
        __half* xrow2 = x2h + (long)tok * DMODEL;
        __half* frow  = fin + (long)tok * DMODEL;
        #pragma unroll
        for (int q = 0; q < 32; q++) {
            int d = q * 32 + lane;
            xrow2[d] = __float2half_rn(vals[q]);
            frow[d]  = __float2half_rn(vals[q] * scale * w[d]);
        }
    }
}

// ------------------- scan over t (per (b,d) row, uint4 fp16 I/O) -----------
__global__ __launch_bounds__(256) void scan_kernel(
    const __half* __restrict__ at, __half* __restrict__ bt)
{
    long base = (long)blockIdx.x * SEQ;
    int tid = threadIdx.x;
    float la[16], lb[16];
    const uint4* ap = (const uint4*)(at + base) + tid * 2;
    uint4*       bp = (uint4*)(bt + base) + tid * 2;
    uint4 va[2] = { ap[0], ap[1] };
    uint4 vb[2] = { bp[0], bp[1] };
    #pragma unroll
    for (int q = 0; q < 8; q++) {
        float2 fa = __half22float2(((const __half2*)va)[q]);
        float2 fb = __half22float2(((const __half2*)vb)[q]);
        la[2*q] = fa.x; la[2*q+1] = fa.y;
        lb[2*q] = fb.x; lb[2*q+1] = fb.y;
    }
    float A = 1.f, Bc = 0.f;
    #pragma unroll
    for (int j = 0; j < 16; j++) { Bc = la[j] * Bc + lb[j]; A *= la[j]; }
    __shared__ float sA[256], sB[256];
    sA[tid] = A; sB[tid] = Bc;
    __syncthreads();
    #pragma unroll
    for (int off = 1; off < 256; off <<= 1) {
        float pA = 1.f, pB = 0.f;
        if (tid >= off) { pA = sA[tid - off]; pB = sB[tid - off]; }
        float cA = sA[tid], cB = sB[tid];
        __syncthreads();
        sA[tid] = pA * cA;
        sB[tid] = cA * pB + cB;
        __syncthreads();
    }
    float carry = (tid > 0) ? sB[tid - 1] : 0.f;
    #pragma unroll
    for (int j = 0; j < 16; j++) { carry = la[j] * carry + lb[j]; lb[j] = carry; }
    #pragma unroll
    for (int q = 0; q < 8; q++)
        ((__half2*)vb)[q] = __floats2half2_rn(lb[2*q], lb[2*q+1]);
    bp[0] = vb[0]; bp[1] = vb[1];
}

// ----------------------------------------------------------------------------
extern "C" void kernel_launch(void* const* d_in, const int* in_sizes, int n_in,
                              void* d_out, int out_size)
{
    const float* x   = (const float*)d_in[0];
    const float* Wg  = (const float*)d_in[1];
    const float* bg  = (const float*)d_in[2];
    const float* Wc  = (const float*)d_in[3];
    const float* bc  = (const float*)d_in[4];
    const float* n1w = (const float*)d_in[5];
    const float* n2w = (const float*)d_in[6];
    const float* W1  = (const float*)d_in[7];
    const float* W3  = (const float*)d_in[8];
    const float* W2  = (const float*)d_in[9];
    float* out = (float*)d_out;

    __half *hin, *fin, *u, *at, *bt, *WgT, *WcT, *W1T, *W3T, *W2T;
    cudaGetSymbolAddress((void**)&hin, g_hin);
    cudaGetSymbolAddress((void**)&fin, g_fin);
    cudaGetSymbolAddress((void**)&at,  g_at);
    cudaGetSymbolAddress((void**)&bt,  g_bt);
    cudaGetSymbolAddress((void**)&u,   g_u);
    cudaGetSymbolAddress((void**)&WgT, g_WgT);
    cudaGetSymbolAddress((void**)&WcT, g_WcT);
    cudaGetSymbolAddress((void**)&W1T, g_W1T);
    cudaGetSymbolAddress((void**)&W3T, g_W3T);
    cudaGetSymbolAddress((void**)&W2T, g_W2T);

    cudaFuncSetAttribute(gemm_dual<M_GATES>, cudaFuncAttributeMaxDynamicSharedMemorySize, DSMEM);
    cudaFuncSetAttribute(gemm_dual<M_FF>,    cudaFuncAttributeMaxDynamicSharedMemorySize, DSMEM);
    cudaFuncSetAttribute(gemm_res,           cudaFuncAttributeMaxDynamicSharedMemorySize, SSMEM);
    cudaFuncSetAttribute(fuse_res_norm,      cudaFuncAttributeMaxDynamicSharedMemorySize, FRSMEM);

    // 0+1) rmsnorm1 + all weight transposes in ONE launch
    prep_kernel<<<MTOK + 14336, 256>>>(x, n1w, hin,
                                       Wg, Wc, W1, W3, W2,
                                       WgT, WcT, W1T, W3T, W2T);

    // 2) dual gates GEMM -> at = sigmoid(.), bt = (1-g)*tanh(.) in [b,d,t] fp16
    gemm_dual<M_GATES><<<dim3(DMODEL/BN, MTOK/BM), 512, DSMEM>>>(
        hin, WgT, WcT, at, bt, nullptr, bg, bc, DMODEL);

    // 3) linear-recurrence scan along t (in place in bt, fp32 compute)
    scan_kernel<<<BATCH * DMODEL, 256>>>(at, bt);

    // 4+5) x2h = half(x + h) (hin reused); fin = half(rmsnorm(x2)*n2w)
    fuse_res_norm<<<dim3(SEQ/32, BATCH), 256, FRSMEM>>>(x, bt, n2w, hin, fin);

    // 6) dual FF GEMM -> u = half(silu(fin@W1T) * (fin@W3T)), coalesced writes
    gemm_dual<M_FF><<<dim3(DFF/BN, MTOK/BM), 512, DSMEM>>>(
        fin, W1T, W3T, nullptr, nullptr, u, nullptr, nullptr, DMODEL);

    // 7) out = x2h + u@W2T (fp16 residual read; final f32 output)
    gemm_res<<<dim3(DMODEL/BN, MTOK/BM), 256, SSMEM>>>(u, W2T, hin, out, DFF, DMODEL);
}

// round 17
// speedup vs baseline: 1.1277x; 1.0292x over previous
#include <cuda_runtime.h>
#include <cuda_fp16.h>
#include <math.h>
#include <stdint.h>

#define BATCH 4
#define SEQ   4096
#define DMODEL 1024
#define DFF   4096
#define MTOK  (BATCH*SEQ)

// ---- dual-B kernel: 512 threads, BKK=64, 4 stages ----
#define BM 128
#define BN 128
#define DKK 64
#define HSTR_D 72                                    // 64 + 8 pad halfs
#define DSTAGES 4
#define DSTAGE_HALFS ((BM + 2*BN) * HSTR_D)          // 27648 halfs = 55296 B
#define DSMEM (DSTAGES * DSTAGE_HALFS * 2)           // 221184

// ---- single-B (W2): 256 threads, BKK=32, 4 stages, 2 CTAs/SM ----
#define SKK 32
#define HSTR_S 40
#define SSTAGES 4
#define SSTAGE_HALFS ((BM + BN) * HSTR_S)            // 10240 halfs = 20480 B
#define SSMEM (SSTAGES * SSTAGE_HALFS * 2)           // 81920

#define M_GATES 0
#define M_FF    1

// fused residual+norm kernel: fp16 slab, 256 threads, 2 CTAs/SM
#define FR_HSTR 1026
#define FRSMEM (32 * FR_HSTR * 2)                    // 65664

// ------------------------- scratch -----------------------------------------
__device__ __half g_hin[MTOK*DMODEL];                // rmsnorm1 out; REUSED as x2 fp16
__device__ __half g_fin[MTOK*DMODEL];
__device__ __half g_at [BATCH*DMODEL*SEQ];           // gates, fp16 [b,d,t]
__device__ __half g_bt [BATCH*DMODEL*SEQ];           // (1-g)*c -> h, fp16 [b,d,t]
__device__ __half g_u  [(size_t)MTOK*DFF];
__device__ __half g_WgT[DMODEL*DMODEL];
__device__ __half g_WcT[DMODEL*DMODEL];
__device__ __half g_W1T[(size_t)DFF*DMODEL];
__device__ __half g_W3T[(size_t)DFF*DMODEL];
__device__ __half g_W2T[(size_t)DMODEL*DFF];

// ------------------------- helpers -----------------------------------------
__device__ __forceinline__ uint32_t smem_u32(const void* p) {
    uint32_t a;
    asm("{ .reg .u64 t; cvta.to.shared.u64 t, %1; cvt.u32.u64 %0, t; }"
        : "=r"(a) : "l"(p));
    return a;
}
#define CPA16(dst, src) \
    asm volatile("cp.async.cg.shared.global [%0], [%1], 16;" :: "r"(dst), "l"(src))
#define CPA_COMMIT() asm volatile("cp.async.commit_group;" ::: "memory")
#define CPA_WAITG(n) asm volatile("cp.async.wait_group %0;" :: "n"(n) : "memory")

__device__ __forceinline__ void hmma(float c[4], const uint32_t a[4], const uint32_t b[2]) {
    asm volatile(
        "mma.sync.aligned.m16n8k16.row.col.f32.f16.f16.f32 "
        "{%0,%1,%2,%3},{%4,%5,%6,%7},{%8,%9},{%0,%1,%2,%3};"
        : "+f"(c[0]), "+f"(c[1]), "+f"(c[2]), "+f"(c[3])
        : "r"(a[0]), "r"(a[1]), "r"(a[2]), "r"(a[3]), "r"(b[0]), "r"(b[1]));
}
__device__ __forceinline__ void ldsm4(uint32_t& r0, uint32_t& r1, uint32_t& r2,
                                      uint32_t& r3, uint32_t addr) {
    asm volatile("ldmatrix.sync.aligned.m8n8.x4.shared.b16 {%0,%1,%2,%3}, [%4];"
                 : "=r"(r0), "=r"(r1), "=r"(r2), "=r"(r3) : "r"(addr));
}
__device__ __forceinline__ int a_lm_off(int lane, int stride) {
    return (lane & 15) * stride + 8 * (lane >> 4);
}
__device__ __forceinline__ int b_lm_off(int lane, int stride) {
    return ((lane & 7) + 8 * (lane >> 4)) * stride + 8 * ((lane >> 3) & 1);
}

// ------------------------- dual-B fp16 GEMM (512 thr, 4 stages) ------------
// Next-stage cp.async spread across ks iterations (2 per ks, commit at ks=2).
template<int MODE>
__global__ __launch_bounds__(512, 1) void gemm_dual(
    const __half* __restrict__ A, const __half* __restrict__ B1T,
    const __half* __restrict__ B2T,
    __half* __restrict__ O1, __half* __restrict__ O2, __half* __restrict__ OU,
    const float* __restrict__ bias1, const float* __restrict__ bias2,
    int K)
{
    extern __shared__ __half smh[];
    const uint32_t sbase = smem_u32(smh);
    const int tid = threadIdx.x, lane = tid & 31, wid = tid >> 5;
    const int wm = wid & 3, wn = wid >> 2;     // 4x4 warps, 32x32 tile each
    const int m0 = blockIdx.y * BM, n0 = blockIdx.x * BN;
    const int NK = K / DKK;

    const int aoff = a_lm_off(lane, HSTR_D);
    const int boff = b_lm_off(lane, HSTR_D);

    float acc1[2][4][4] = {};
    float acc2[2][4][4] = {};

    #define DPART(stage, ktile, p0, p1)                                           \
    {                                                                             \
        uint32_t base = sbase + (stage) * DSTAGE_HALFS * 2;                       \
        long koff = (long)(ktile) * DKK;                                          \
        _Pragma("unroll")                                                         \
        for (int i = (p0); i < (p1); i++) {                                       \
            int id = tid + i * 512;                                               \
            int row = id >> 3, ch = (id & 7) * 8;                                 \
            const __half* src;                                                    \
            if (row < 128)      src = A   + (long)(m0 + row)       * K + koff + ch; \
            else if (row < 256) src = B1T + (long)(n0 + row - 128) * K + koff + ch; \
            else                src = B2T + (long)(n0 + row - 256) * K + koff + ch; \
            CPA16(base + (row * HSTR_D + ch) * 2, src);                           \
        }                                                                         \
    }

    #pragma unroll
    for (int ps = 0; ps < DSTAGES - 1; ps++) { DPART(ps, ps, 0, 6); CPA_COMMIT(); }

    for (int kt = 0; kt < NK; kt++) {
        CPA_WAITG(DSTAGES - 2);
        __syncthreads();
        const int nxt = kt + DSTAGES - 1;
        const int nst = nxt % DSTAGES;
        const bool more = (nxt < NK);

        uint32_t stg = sbase + (kt % DSTAGES) * DSTAGE_HALFS * 2;
        uint32_t As  = stg;
        uint32_t B1s = stg + BM * HSTR_D * 2;
        uint32_t B2s = stg + (BM + BN) * HSTR_D * 2;
        #pragma unroll
        for (int ks = 0; ks < 4; ks++) {
            if (ks < 3 && more) DPART(nst, nxt, ks * 2, ks * 2 + 2);
            if (ks == 2) CPA_COMMIT();

            const int k0 = ks * 16;
            uint32_t af[2][4], bf1[4][2], bf2[4][2];
            #pragma unroll
            for (int i = 0; i < 2; i++) {
                uint32_t ad = As + ((wm*32 + i*16) * HSTR_D + k0 + aoff) * 2;
                ldsm4(af[i][0], af[i][1], af[i][2], af[i][3], ad);
            }
            #pragma unroll
            for (int jp = 0; jp < 2; jp++) {
                uint32_t bd1 = B1s + ((wn*32 + jp*16) * HSTR_D + k0 + boff) * 2;
                uint32_t bd2 = B2s + ((wn*32 + jp*16) * HSTR_D + k0 + boff) * 2;
                ldsm4(bf1[jp*2][0], bf1[jp*2][1], bf1[jp*2+1][0], bf1[jp*2+1][1], bd1);
                ldsm4(bf2[jp*2][0], bf2[jp*2][1], bf2[jp*2+1][0], bf2[jp*2+1][1], bd2);
            }
            #pragma unroll
            for (int i = 0; i < 2; i++)
                #pragma unroll
                for (int j = 0; j < 4; j++) {
                    hmma(acc1[i][j], af[i], bf1[j]);
                    hmma(acc2[i][j], af[i], bf2[j]);
                }
        }
    }
    __syncthreads();   // smem reused for epilogue patches

    if (MODE == M_FF) {
        __half2* patch = (__half2*)smh + wid * (32 * 36);
        #pragma unroll
        for (int i = 0; i < 2; i++) {
            #pragma unroll
            for (int j = 0; j < 4; j++) {
                int r0 = i*16 + (lane>>2);
                int ch = j*4 + (lane&3);
                float a0 = acc1[i][j][0], a1 = acc1[i][j][1];
                float a2 = acc1[i][j][2], a3 = acc1[i][j][3];
                float v0 = a0 / (1.f + __expf(-a0)) * acc2[i][j][0];
                float v1 = a1 / (1.f + __expf(-a1)) * acc2[i][j][1];
                float v2 = a2 / (1.f + __expf(-a2)) * acc2[i][j][2];
                float v3 = a3 / (1.f + __expf(-a3)) * acc2[i][j][3];
                patch[r0*36 + ch]     = __floats2half2_rn(v0, v1);
                patch[(r0+8)*36 + ch] = __floats2half2_rn(v2, v3);
            }
        }
        __syncwarp();
        int tok0 = m0 + wm * 32;
        int cb = n0 + wn * 32;
        #pragma unroll
        for (int r2 = 0; r2 < 32; r2 += 2) {
            int rr = r2 + (lane >> 4);
            int cc = lane & 15;
            *(__half2*)(OU + (long)(tok0 + rr) * DFF + cb + cc*2) = patch[rr*36 + cc];
        }
    } else {
        float* patchG = (float*)smh + wid * 2 * (32 * 33);
        float* patchH = patchG + 32 * 33;
        #pragma unroll
        for (int i = 0; i < 2; i++) {
            #pragma unroll
            for (int j = 0; j < 4; j++) {
                int r0 = i*16 + (lane>>2);            // t-local 0..31
                int c0 = j*8 + 2*(lane&3);            // n-local 0..31
                int n  = n0 + wn*32 + c0;
                float b1a = bias1[n], b1b = bias1[n+1];
                float b2a = bias2[n], b2b = bias2[n+1];
                float g0 = 1.f / (1.f + __expf(-(acc1[i][j][0] + b1a)));
                float g1 = 1.f / (1.f + __expf(-(acc1[i][j][1] + b1b)));
                float g2 = 1.f / (1.f + __expf(-(acc1[i][j][2] + b1a)));
                float g3 = 1.f / (1.f + __expf(-(acc1[i][j][3] + b1b)));
                float h0 = (1.f - g0) * tanhf(acc2[i][j][0] + b2a);
                float h1 = (1.f - g1) * tanhf(acc2[i][j][1] + b2b);
                float h2 = (1.f - g2) * tanhf(acc2[i][j][2] + b2a);
                float h3 = (1.f - g3) * tanhf(acc2[i][j][3] + b2b);
                patchG[c0*33 + r0]       = g0;
                patchG[(c0+1)*33 + r0]   = g1;
                patchG[c0*33 + r0+8]     = g2;
                patchG[(c0+1)*33 + r0+8] = g3;
                patchH[c0*33 + r0]       = h0;
                patchH[(c0+1)*33 + r0]   = h1;
                patchH[c0*33 + r0+8]     = h2;
                patchH[(c0+1)*33 + r0+8] = h3;
            }
        }
        __syncwarp();
        int tokb = m0 + wm * 32;
        int b = tokb >> 12, tb = tokb & 4095;
        #pragma unroll 4
        for (int r = 0; r < 32; r++) {
            int n = n0 + wn*32 + r;
            long off = ((long)(b * DMODEL + n)) * SEQ + tb + lane;
            O1[off] = __float2half_rn(patchG[r*33 + lane]);
            O2[off] = __float2half_rn(patchH[r*33 + lane]);
        }
    }
    #undef DPART
}

// --------- single-B fp16 GEMM: O = X2(fp16) + A@BT^T (final output) --------
// Next-stage cp.async spread across ks iterations (2 per ks, commit at ks=1).
__global__ __launch_bounds__(256, 2) void gemm_res(
    const __half* __restrict__ A, const __half* __restrict__ BT,
    const __half* __restrict__ X2, float* __restrict__ O, int K, int ldo)
{
    extern __shared__ __half smh[];
    const uint32_t sbase = smem_u32(smh);
    const int tid = threadIdx.x, lane = tid & 31, wid = tid >> 5;
    const int wm = wid & 1, wn = wid >> 1;
    const int m0 = blockIdx.y * BM, n0 = blockIdx.x * BN;
    const int NK = K / SKK;

    const int aoff = a_lm_off(lane, HSTR_S);
    const int boff = b_lm_off(lane, HSTR_S);

    float acc[4][4][4] = {};

    #define SPART(stage, ktile, p0, p1)                                            \
    {                                                                             \
        uint32_t base = sbase + (stage) * SSTAGE_HALFS * 2;                       \
        long koff = (long)(ktile) * SKK;                                          \
        _Pragma("unroll")                                                         \
        for (int i = (p0); i < (p1); i++) {                                       \
            int id = tid + i * 256;                                               \
            int row = id >> 2, ch = (id & 3) * 8;                                 \
            const __half* src;                                                    \
            if (row < 128) src = A  + (long)(m0 + row)       * K + koff + ch;     \
            else           src = BT + (long)(n0 + row - 128) * K + koff + ch;     \
            CPA16(base + (row * HSTR_S + ch) * 2, src);                           \
        }                                                                         \
    }

    #pragma unroll
    for (int ps = 0; ps < SSTAGES - 1; ps++) { SPART(ps, ps, 0, 4); CPA_COMMIT(); }

    for (int kt = 0; kt < NK; kt++) {
        CPA_WAITG(SSTAGES - 2);
        __syncthreads();
        const int nxt = kt + SSTAGES - 1;
        const int nst = nxt % SSTAGES;
        const bool more = (nxt < NK);

        uint32_t stg = sbase + (kt % SSTAGES) * SSTAGE_HALFS * 2;
        uint32_t As = stg;
        uint32_t Bs = stg + BM * HSTR_S * 2;
        #pragma unroll
        for (int ks = 0; ks < 2; ks++) {
            if (more) SPART(nst, nxt, ks * 2, ks * 2 + 2);
            if (ks == 1) CPA_COMMIT();

            const int k0 = ks * 16;
            uint32_t af[4][4], bf[4][2];
            #pragma unroll
            for (int i = 0; i < 4; i++) {
                uint32_t ad = As + ((wm*64 + i*16) * HSTR_S + k0 + aoff) * 2;
                ldsm4(af[i][0], af[i][1], af[i][2], af[i][3], ad);
            }
            #pragma unroll
            for (int jp = 0; jp < 2; jp++) {
                uint32_t bd = Bs + ((wn*32 + jp*16) * HSTR_S + k0 + boff) * 2;
                ldsm4(bf[jp*2][0], bf[jp*2][1], bf[jp*2+1][0], bf[jp*2+1][1], bd);
            }
            #pragma unroll
            for (int i = 0; i < 4; i++)
                #pragma unroll
                for (int j = 0; j < 4; j++)
                    hmma(acc[i][j], af[i], bf[j]);
        }
    }

    #pragma unroll
    for (int i = 0; i < 4; i++) {
        #pragma unroll
        for (int j = 0; j < 4; j++) {
            int r0 = m0 + wm*64 + i*16 + (lane>>2);
            int c0 = n0 + wn*32 + j*8 + 2*(lane&3);
            long o0 = (long)r0 * ldo + c0;
            long o1 = o0 + (long)8 * ldo;
            float2 p0 = __half22float2(*(const __half2*)(X2 + o0));
            float2 p1 = __half22float2(*(const __half2*)(X2 + o1));
            *(float2*)(O + o0) = make_float2(acc[i][j][0] + p0.x, acc[i][j][1] + p0.y);
            *(float2*)(O + o1) = make_float2(acc[i][j][2] + p1.x, acc[i][j][3] + p1.y);
        }
    }
    #undef SPART
}

// ------ prep: rmsnorm (blocks < MTOK) + all weight transposes (rest) -------
__global__ __launch_bounds__(256) void prep_kernel(
    const float* __restrict__ x, const float* __restrict__ w, __half* __restrict__ y,
    const float* __restrict__ Wg, const float* __restrict__ Wc,
    const float* __restrict__ W1, const float* __restrict__ W3,
    const float* __restrict__ W2,
    __half* __restrict__ WgT, __half* __restrict__ WcT,
    __half* __restrict__ W1T, __half* __restrict__ W3T,
    __half* __restrict__ W2T)
{
    __shared__ float sred[8];
    __shared__ float tile[32][33];
    int bid = blockIdx.x, tid = threadIdx.x;

    if (bid >= MTOK) {
        int s = bid - MTOK;                    // 0..14335
        const float* W; __half* WT; int Kw, Nw, tt;
        if (s < 1024)       { W = Wg; WT = WgT; Kw = DMODEL; Nw = DMODEL; tt = s; }
        else if (s < 2048)  { W = Wc; WT = WcT; Kw = DMODEL; Nw = DMODEL; tt = s - 1024; }
        else if (s < 6144)  { W = W1; WT = W1T; Kw = DMODEL; Nw = DFF;    tt = s - 2048; }
        else if (s < 10240) { W = W3; WT = W3T; Kw = DMODEL; Nw = DFF;    tt = s - 6144; }
        else                { W = W2; WT = W2T; Kw = DFF;    Nw = DMODEL; tt = s - 10240; }
        int ntx = Nw >> 5;
        int n0 = (tt % ntx) * 32, k0 = (tt / ntx) * 32;
        int tx = tid & 31, ty = tid >> 5;
        #pragma unroll
        for (int i = 0; i < 4; i++)
            tile[ty + 8*i][tx] = W[(long)(k0 + ty + 8*i) * Nw + n0 + tx];
        __syncthreads();
        #pragma unroll
        for (int i = 0; i < 4; i++)
            WT[(long)(n0 + ty + 8*i) * Kw + k0 + tx] =
                __float2half_rn(tile[tx][ty + 8*i]);
        return;
    }

    float4 v = ((const float4*)(x + (long)bid * DMODEL))[tid];
    float ss = v.x*v.x + v.y*v.y + v.z*v.z + v.w*v.w;
    #pragma unroll
    for (int o = 16; o; o >>= 1) ss += __shfl_xor_sync(0xffffffffu, ss, o);
    if ((tid & 31) == 0) sred[tid >> 5] = ss;
    __syncthreads();
    if (tid < 8) {
        float t = sred[tid];
        #pragma unroll
        for (int o = 4; o; o >>= 1) t += __shfl_xor_sync(0xffu, t, o);
        if (tid == 0) sred[0] = t;
    }
    __syncthreads();
    float scale = rsqrtf(sred[0] * (1.0f / DMODEL) + 1e-6f);
    float4 wv = ((const float4*)w)[tid];
    __half2 h01 = __floats2half2_rn(v.x*scale*wv.x, v.y*scale*wv.y);
    __half2 h23 = __floats2half2_rn(v.z*scale*wv.z, v.w*scale*wv.w);
    __half2* yp = (__half2*)(y + (long)bid * DMODEL) + tid * 2;
    yp[0] = h01; yp[1] = h23;
}

// ---- fused: x2 = x + h^T; x2h = half(x2); fin = half(rmsnorm(x2)*w) --------
__global__ __launch_bounds__(256) void fuse_res_norm(
    const float* __restrict__ x, const __half* __restrict__ ht,
    const float* __restrict__ w,
    __half* __restrict__ x2h, __half* __restrict__ fin)
{
    extern __shared__ __half hslab[];          // [32][FR_HSTR]
    const int t0 = blockIdx.x * 32, b = blockIdx.y;
    const int tid = threadIdx.x, lane = tid & 31, wid = tid >> 5;

    for (int g = 0; g < 4; g++) {
        for (int dc = 0; dc < 32; dc++) {
            int d = g * 256 + dc * 8 + wid;
            const __half* src = ht + ((long)(b * DMODEL + d)) * SEQ + t0;
            hslab[lane * FR_HSTR + d] = src[lane];
        }
    }
    __syncthreads();

    #pragma unroll
    for (int k = 0; k < 4; k++) {
        int tt = wid * 4 + k;
        int tok = b * SEQ + t0 + tt;
        const __half* row = hslab + tt * FR_HSTR;
        const float* xr = x + (long)tok * DMODEL;
        float ss = 0.f;
        float vals[32];
        #pragma unroll
        for (int q = 0; q < 32; q++) {
            float v = xr[q * 32 + lane] + __half2float(row[q * 32 + lane]);
            vals[q] = v;
            ss += v * v;
        }
        #pragma unroll
        for (int o = 16; o; o >>= 1) ss += __shfl_xor_sync(0xffffffffu, ss, o);
        float scale = rsqrtf(ss * (1.0f / DMODEL) + 1e-6f);
        __half* xrow2 = x2h + (long)tok * DMODEL;
        __half* frow  = fin + (long)tok * DMODEL;
        #pragma unroll
        for (int q = 0; q < 32; q++) {
            int d = q * 32 + lane;
            xrow2[d] = __float2half_rn(vals[q]);
            frow[d]  = __float2half_rn(vals[q] * scale * w[d]);
        }
    }
}

// ------------------- scan over t (per (b,d) row, uint4 fp16 I/O) -----------
__global__ __launch_bounds__(256) void scan_kernel(
    const __half* __restrict__ at, __half* __restrict__ bt)
{
    long base = (long)blockIdx.x * SEQ;
    int tid = threadIdx.x;
    float la[16], lb[16];
    const uint4* ap = (const uint4*)(at + base) + tid * 2;
    uint4*       bp = (uint4*)(bt + base) + tid * 2;
    uint4 va[2] = { ap[0], ap[1] };
    uint4 vb[2] = { bp[0], bp[1] };
    #pragma unroll
    for (int q = 0; q < 8; q++) {
        float2 fa = __half22float2(((const __half2*)va)[q]);
        float2 fb = __half22float2(((const __half2*)vb)[q]);
        la[2*q] = fa.x; la[2*q+1] = fa.y;
        lb[2*q] = fb.x; lb[2*q+1] = fb.y;
    }
    float A = 1.f, Bc = 0.f;
    #pragma unroll
    for (int j = 0; j < 16; j++) { Bc = la[j] * Bc + lb[j]; A *= la[j]; }
    __shared__ float sA[256], sB[256];
    sA[tid] = A; sB[tid] = Bc;
    __syncthreads();
    #pragma unroll
    for (int off = 1; off < 256; off <<= 1) {
        float pA = 1.f, pB = 0.f;
        if (tid >= off) { pA = sA[tid - off]; pB = sB[tid - off]; }
        float cA = sA[tid], cB = sB[tid];
        __syncthreads();
        sA[tid] = pA * cA;
        sB[tid] = cA * pB + cB;
        __syncthreads();
    }
    float carry = (tid > 0) ? sB[tid - 1] : 0.f;
    #pragma unroll
    for (int j = 0; j < 16; j++) { carry = la[j] * carry + lb[j]; lb[j] = carry; }
    #pragma unroll
    for (int q = 0; q < 8; q++)
        ((__half2*)vb)[q] = __floats2half2_rn(lb[2*q], lb[2*q+1]);
    bp[0] = vb[0]; bp[1] = vb[1];
}

// ----------------------------------------------------------------------------
extern "C" void kernel_launch(void* const* d_in, const int* in_sizes, int n_in,
                              void* d_out, int out_size)
{
    const float* x   = (const float*)d_in[0];
    const float* Wg  = (const float*)d_in[1];
    const float* bg  = (const float*)d_in[2];
    const float* Wc  = (const float*)d_in[3];
    const float* bc  = (const float*)d_in[4];
    const float* n1w = (const float*)d_in[5];
    const float* n2w = (const float*)d_in[6];
    const float* W1  = (const float*)d_in[7];
    const float* W3  = (const float*)d_in[8];
    const float* W2  = (const float*)d_in[9];
    float* out = (float*)d_out;

    __half *hin, *fin, *u, *at, *bt, *WgT, *WcT, *W1T, *W3T, *W2T;
    cudaGetSymbolAddress((void**)&hin, g_hin);
    cudaGetSymbolAddress((void**)&fin, g_fin);
    cudaGetSymbolAddress((void**)&at,  g_at);
    cudaGetSymbolAddress((void**)&bt,  g_bt);
    cudaGetSymbolAddress((void**)&u,   g_u);
    cudaGetSymbolAddress((void**)&WgT, g_WgT);
    cudaGetSymbolAddress((void**)&WcT, g_WcT);
    cudaGetSymbolAddress((void**)&W1T, g_W1T);
    cudaGetSymbolAddress((void**)&W3T, g_W3T);
    cudaGetSymbolAddress((void**)&W2T, g_W2T);

    cudaFuncSetAttribute(gemm_dual<M_GATES>, cudaFuncAttributeMaxDynamicSharedMemorySize, DSMEM);
    cudaFuncSetAttribute(gemm_dual<M_FF>,    cudaFuncAttributeMaxDynamicSharedMemorySize, DSMEM);
    cudaFuncSetAttribute(gemm_res,           cudaFuncAttributeMaxDynamicSharedMemorySize, SSMEM);
    cudaFuncSetAttribute(fuse_res_norm,      cudaFuncAttributeMaxDynamicSharedMemorySize, FRSMEM);

    // 0+1) rmsnorm1 + all weight transposes in ONE launch
    prep_kernel<<<MTOK + 14336, 256>>>(x, n1w, hin,
                                       Wg, Wc, W1, W3, W2,
                                       WgT, WcT, W1T, W3T, W2T);

    // 2) dual gates GEMM -> at = sigmoid(.), bt = (1-g)*tanh(.) in [b,d,t] fp16
    gemm_dual<M_GATES><<<dim3(DMODEL/BN, MTOK/BM), 512, DSMEM>>>(
        hin, WgT, WcT, at, bt, nullptr, bg, bc, DMODEL);

    // 3) linear-recurrence scan along t (in place in bt, fp32 compute)
    scan_kernel<<<BATCH * DMODEL, 256>>>(at, bt);

    // 4+5) x2h = half(x + h) (hin reused); fin = half(rmsnorm(x2)*n2w)
    fuse_res_norm<<<dim3(SEQ/32, BATCH), 256, FRSMEM>>>(x, bt, n2w, hin, fin);

    // 6) dual FF GEMM -> u = half(silu(fin@W1T) * (fin@W3T)), coalesced writes
    gemm_dual<M_FF><<<dim3(DFF/BN, MTOK/BM), 512, DSMEM>>>(
        fin, W1T, W3T, nullptr, nullptr, u, nullptr, nullptr, DMODEL);

    // 7) out = x2h + u@W2T (fp16 residual read; final f32 output)
    gemm_res<<<dim3(DMODEL/BN, MTOK/BM), 256, SSMEM>>>(u, W2T, hin, out, DFF, DMODEL);
}